// round 1
// baseline (speedup 1.0000x reference)
#include <cuda_runtime.h>
#include <math.h>

#define BATCH_ 2
#define SEQ    2048
#define DIMV   4096
#define NH     32
#define NKV    8
#define HD     128
#define TOKENS (BATCH_*SEQ)   // 4096

// ---------------- scratch (no cudaMalloc allowed) ----------------
__device__ float g_q  [(size_t)TOKENS * NH  * HD];   // 64 MB
__device__ float g_k  [(size_t)TOKENS * NKV * HD];   // 16 MB
__device__ float g_v  [(size_t)TOKENS * NKV * HD];   // 16 MB
__device__ float g_att[(size_t)TOKENS * NH  * HD];   // 64 MB

// ================= SGEMM: C[M,N] = A[M,K] @ B[K,N], all row-major, fp32 =====
// 128x128 tile, BK=16, 256 threads, 8x8 per thread.
__global__ void __launch_bounds__(256) sgemm128(
    const float* __restrict__ A, const float* __restrict__ B,
    float* __restrict__ C, int M, int N, int K)
{
    __shared__ float As[16 * 136];   // As[k][m], padded stride 136 (16B-aligned rows)
    __shared__ float Bs[16 * 128];   // Bs[k][n]

    const int tid = threadIdx.x;
    const int tx = tid & 15, ty = tid >> 4;
    const int row0 = blockIdx.y * 128;
    const int col0 = blockIdx.x * 128;

    float acc[8][8];
#pragma unroll
    for (int i = 0; i < 8; i++)
#pragma unroll
        for (int j = 0; j < 8; j++) acc[i][j] = 0.f;

    for (int k0 = 0; k0 < K; k0 += 16) {
#pragma unroll
        for (int t = 0; t < 2; t++) {
            int p = tid + t * 256;
            int ar = p >> 2, ac = (p & 3) << 2;
            float4 av = *(const float4*)(A + (size_t)(row0 + ar) * K + k0 + ac);
            As[(ac + 0) * 136 + ar] = av.x;
            As[(ac + 1) * 136 + ar] = av.y;
            As[(ac + 2) * 136 + ar] = av.z;
            As[(ac + 3) * 136 + ar] = av.w;
            int br = p >> 5, bc = (p & 31) << 2;
            float4 bv = *(const float4*)(B + (size_t)(k0 + br) * N + col0 + bc);
            *(float4*)&Bs[br * 128 + bc] = bv;
        }
        __syncthreads();
#pragma unroll
        for (int kk = 0; kk < 16; kk++) {
            float4 a0 = *(const float4*)&As[kk * 136 + ty * 8];
            float4 a1 = *(const float4*)&As[kk * 136 + ty * 8 + 4];
            float4 b0 = *(const float4*)&Bs[kk * 128 + tx * 8];
            float4 b1 = *(const float4*)&Bs[kk * 128 + tx * 8 + 4];
            float a[8] = {a0.x, a0.y, a0.z, a0.w, a1.x, a1.y, a1.z, a1.w};
            float b[8] = {b0.x, b0.y, b0.z, b0.w, b1.x, b1.y, b1.z, b1.w};
#pragma unroll
            for (int i = 0; i < 8; i++)
#pragma unroll
                for (int j = 0; j < 8; j++) acc[i][j] = fmaf(a[i], b[j], acc[i][j]);
        }
        __syncthreads();
    }

#pragma unroll
    for (int i = 0; i < 8; i++) {
        int row = row0 + ty * 8 + i;
        float4 c0 = make_float4(acc[i][0], acc[i][1], acc[i][2], acc[i][3]);
        float4 c1 = make_float4(acc[i][4], acc[i][5], acc[i][6], acc[i][7]);
        *(float4*)(C + (size_t)row * N + col0 + tx * 8)     = c0;
        *(float4*)(C + (size_t)row * N + col0 + tx * 8 + 4) = c1;
    }
}

// ================= RoPE (in place), layout [B,S,H,HD] ======================
__global__ void rope_kernel(float* __restrict__ t,
                            const float* __restrict__ fc,
                            const float* __restrict__ fs, int nheads, int total)
{
    int idx = blockIdx.x * blockDim.x + threadIdx.x;
    if (idx >= total) return;
    int j = idx & 63;
    int s = (idx / (64 * nheads)) % SEQ;
    float c  = fc[s * 64 + j];
    float sn = fs[s * 64 + j];
    float* p = t + (size_t)idx * 2;
    float re = p[0], im = p[1];
    p[0] = re * c - im * sn;
    p[1] = re * sn + im * c;
}

// ================= Flash attention, fp32, causal, GQA =====================
// Block: one (b, h, q-tile of 64). 256 threads as 16x16; per thread:
//   S phase: 4x4 sub-tile of S[64,64];  PV phase: 4 rows x 8 cols of O[64,128].
#define ATTN_SMEM ((128*72*2 + 64*132 + 64*68) * 4)

__global__ void __launch_bounds__(256, 1) attn_kernel(
    const float* __restrict__ Q, const float* __restrict__ K,
    const float* __restrict__ V, float* __restrict__ O)
{
    extern __shared__ float sm[];
    float* Qt = sm;                 // [128][72]  Qt[d][r]   (Q transposed, pre-scaled)
    float* Kt = Qt + 128 * 72;      // [128][72]  Kt[d][kc]  (K transposed)
    float* Vs = Kt + 128 * 72;      // [64][132]  Vs[kc][d]
    float* Ps = Vs + 64 * 132;      // [64][68]   P tile

    const int tid = threadIdx.x;
    const int tx = tid & 15, ty = tid >> 4;
    const int qt = blockIdx.x, h = blockIdx.y, b = blockIdx.z;
    const int q0 = qt * 64;
    const int kvh = h >> 2;                    // N_REP = 4

    const float* Qb = Q + (((size_t)b * SEQ) * NH  + h)   * HD;
    const float* Kb = K + (((size_t)b * SEQ) * NKV + kvh) * HD;
    const float* Vb = V + (((size_t)b * SEQ) * NKV + kvh) * HD;

    const float scale = 0.08838834764831845f;  // 1/sqrt(128)

    // load Q tile transposed (folding softmax scale)
#pragma unroll
    for (int i = tid; i < 64 * 32; i += 256) {
        int r = i >> 5, c4 = (i & 31) << 2;
        float4 qv = *(const float4*)(Qb + (size_t)(q0 + r) * (NH * HD) + c4);
        Qt[(c4 + 0) * 72 + r] = qv.x * scale;
        Qt[(c4 + 1) * 72 + r] = qv.y * scale;
        Qt[(c4 + 2) * 72 + r] = qv.z * scale;
        Qt[(c4 + 3) * 72 + r] = qv.w * scale;
    }

    float acc[4][8];
#pragma unroll
    for (int i = 0; i < 4; i++)
#pragma unroll
        for (int j = 0; j < 8; j++) acc[i][j] = 0.f;
    float mrow[4] = {-1e30f, -1e30f, -1e30f, -1e30f};
    float lrow[4] = {0.f, 0.f, 0.f, 0.f};

    for (int kt = 0; kt <= qt; kt++) {
        const int k0 = kt * 64;
        __syncthreads();   // protect Kt/Vs/Ps from previous iteration readers
#pragma unroll
        for (int i = tid; i < 64 * 32; i += 256) {
            int r = i >> 5, c4 = (i & 31) << 2;
            float4 kv = *(const float4*)(Kb + (size_t)(k0 + r) * (NKV * HD) + c4);
            Kt[(c4 + 0) * 72 + r] = kv.x;
            Kt[(c4 + 1) * 72 + r] = kv.y;
            Kt[(c4 + 2) * 72 + r] = kv.z;
            Kt[(c4 + 3) * 72 + r] = kv.w;
            float4 vv = *(const float4*)(Vb + (size_t)(k0 + r) * (NKV * HD) + c4);
            *(float4*)(Vs + r * 132 + c4) = vv;
        }
        __syncthreads();

        // ---- S = Q K^T (4x4 per thread) ----
        float s[4][4];
#pragma unroll
        for (int i = 0; i < 4; i++)
#pragma unroll
            for (int j = 0; j < 4; j++) s[i][j] = 0.f;

#pragma unroll 4
        for (int d = 0; d < 128; d++) {
            float4 aa = *(const float4*)(Qt + d * 72 + ty * 4);
            float4 bb = *(const float4*)(Kt + d * 72 + tx * 4);
            float a[4] = {aa.x, aa.y, aa.z, aa.w};
            float bv[4] = {bb.x, bb.y, bb.z, bb.w};
#pragma unroll
            for (int i = 0; i < 4; i++)
#pragma unroll
                for (int j = 0; j < 4; j++) s[i][j] = fmaf(a[i], bv[j], s[i][j]);
        }

        if (kt == qt) {   // causal mask on the diagonal tile
#pragma unroll
            for (int i = 0; i < 4; i++)
#pragma unroll
                for (int j = 0; j < 4; j++)
                    if ((k0 + tx * 4 + j) > (q0 + ty * 4 + i)) s[i][j] = -1e30f;
        }

        // ---- online softmax (row stats reduced over the 16-lane ty-group) ----
#pragma unroll
        for (int i = 0; i < 4; i++) {
            float mx = fmaxf(fmaxf(s[i][0], s[i][1]), fmaxf(s[i][2], s[i][3]));
            mx = fmaxf(mx, __shfl_xor_sync(0xffffffffu, mx, 8));
            mx = fmaxf(mx, __shfl_xor_sync(0xffffffffu, mx, 4));
            mx = fmaxf(mx, __shfl_xor_sync(0xffffffffu, mx, 2));
            mx = fmaxf(mx, __shfl_xor_sync(0xffffffffu, mx, 1));
            float mnew = fmaxf(mrow[i], mx);
            float corr = __expf(mrow[i] - mnew);
            float psum = 0.f;
#pragma unroll
            for (int j = 0; j < 4; j++) {
                float p = __expf(s[i][j] - mnew);
                psum += p;
                Ps[(ty * 4 + i) * 68 + tx * 4 + j] = p;
            }
            psum += __shfl_xor_sync(0xffffffffu, psum, 8);
            psum += __shfl_xor_sync(0xffffffffu, psum, 4);
            psum += __shfl_xor_sync(0xffffffffu, psum, 2);
            psum += __shfl_xor_sync(0xffffffffu, psum, 1);
            lrow[i] = lrow[i] * corr + psum;
            mrow[i] = mnew;
#pragma unroll
            for (int j = 0; j < 8; j++) acc[i][j] *= corr;
        }
        __syncthreads();

        // ---- O += P V (4 rows x 8 cols per thread) ----
#pragma unroll 4
        for (int kk = 0; kk < 64; kk++) {
            float4 v0 = *(const float4*)(Vs + kk * 132 + tx * 8);
            float4 v1 = *(const float4*)(Vs + kk * 132 + tx * 8 + 4);
#pragma unroll
            for (int i = 0; i < 4; i++) {
                float p = Ps[(ty * 4 + i) * 68 + kk];
                acc[i][0] = fmaf(p, v0.x, acc[i][0]);
                acc[i][1] = fmaf(p, v0.y, acc[i][1]);
                acc[i][2] = fmaf(p, v0.z, acc[i][2]);
                acc[i][3] = fmaf(p, v0.w, acc[i][3]);
                acc[i][4] = fmaf(p, v1.x, acc[i][4]);
                acc[i][5] = fmaf(p, v1.y, acc[i][5]);
                acc[i][6] = fmaf(p, v1.z, acc[i][6]);
                acc[i][7] = fmaf(p, v1.w, acc[i][7]);
            }
        }
    }

    // ---- epilogue: normalize + write [B,S,NH,HD] ----
#pragma unroll
    for (int i = 0; i < 4; i++) {
        float inv = 1.f / lrow[i];
        int row = q0 + ty * 4 + i;
        float4 o0 = make_float4(acc[i][0] * inv, acc[i][1] * inv,
                                acc[i][2] * inv, acc[i][3] * inv);
        float4 o1 = make_float4(acc[i][4] * inv, acc[i][5] * inv,
                                acc[i][6] * inv, acc[i][7] * inv);
        float* dst = O + (((size_t)b * SEQ + row) * NH + h) * HD + tx * 8;
        *(float4*)(dst)     = o0;
        *(float4*)(dst + 4) = o1;
    }
}

// ============================ launch ======================================
extern "C" void kernel_launch(void* const* d_in, const int* in_sizes, int n_in,
                              void* d_out, int out_size)
{
    const float* x  = (const float*)d_in[0];
    const float* wq = (const float*)d_in[1];
    const float* wk = (const float*)d_in[2];
    const float* wv = (const float*)d_in[3];
    const float* wo = (const float*)d_in[4];
    const float* fc = (const float*)d_in[7];   // freqs_cos [SEQ, 64]
    const float* fs = (const float*)d_in[8];   // freqs_sin [SEQ, 64]
    float* out = (float*)d_out;
    (void)in_sizes; (void)n_in; (void)out_size;  // start_pos == 0, mask == causal

    float *q, *k, *v, *att;
    cudaGetSymbolAddress((void**)&q,   g_q);
    cudaGetSymbolAddress((void**)&k,   g_k);
    cudaGetSymbolAddress((void**)&v,   g_v);
    cudaGetSymbolAddress((void**)&att, g_att);

    // projections
    sgemm128<<<dim3(NH * HD / 128,  TOKENS / 128), 256>>>(x, wq, q, TOKENS, NH * HD,  DIMV);
    sgemm128<<<dim3(NKV * HD / 128, TOKENS / 128), 256>>>(x, wk, k, TOKENS, NKV * HD, DIMV);
    sgemm128<<<dim3(NKV * HD / 128, TOKENS / 128), 256>>>(x, wv, v, TOKENS, NKV * HD, DIMV);

    // RoPE
    {
        int tq = BATCH_ * SEQ * NH * 64;
        int tk = BATCH_ * SEQ * NKV * 64;
        rope_kernel<<<(tq + 255) / 256, 256>>>(q, fc, fs, NH,  tq);
        rope_kernel<<<(tk + 255) / 256, 256>>>(k, fc, fs, NKV, tk);
    }

    // attention
    cudaFuncSetAttribute(attn_kernel, cudaFuncAttributeMaxDynamicSharedMemorySize, ATTN_SMEM);
    attn_kernel<<<dim3(SEQ / 64, NH, BATCH_), 256, ATTN_SMEM>>>(q, k, v, att);

    // output projection
    sgemm128<<<dim3(DIMV / 128, TOKENS / 128), 256>>>(att, wo, out, TOKENS, DIMV, DIMV);
}

// round 3
// speedup vs baseline: 1.1175x; 1.1175x over previous
#include <cuda_runtime.h>
#include <cuda_bf16.h>
#include <math.h>
#include <stdint.h>

#define BATCH_ 2
#define SEQ    2048
#define DIMV   4096
#define NH     32
#define NKV    8
#define HD     128
#define TOKENS (BATCH_*SEQ)   // 4096

// ---------------- scratch (no cudaMalloc allowed) ----------------
__device__ __align__(1024) float g_q  [(size_t)TOKENS * NH  * HD];
__device__ __align__(1024) float g_k  [(size_t)TOKENS * NKV * HD];
__device__ __align__(1024) float g_v  [(size_t)TOKENS * NKV * HD];
__device__ __align__(1024) float g_att[(size_t)TOKENS * NH  * HD];

__device__ __align__(1024) __nv_bfloat16 g_xh  [(size_t)TOKENS * DIMV];
__device__ __align__(1024) __nv_bfloat16 g_xl  [(size_t)TOKENS * DIMV];
__device__ __align__(1024) __nv_bfloat16 g_wqth[(size_t)DIMV * DIMV];
__device__ __align__(1024) __nv_bfloat16 g_wqtl[(size_t)DIMV * DIMV];
__device__ __align__(1024) __nv_bfloat16 g_wkth[(size_t)(NKV*HD) * DIMV];
__device__ __align__(1024) __nv_bfloat16 g_wktl[(size_t)(NKV*HD) * DIMV];
__device__ __align__(1024) __nv_bfloat16 g_wvth[(size_t)(NKV*HD) * DIMV];
__device__ __align__(1024) __nv_bfloat16 g_wvtl[(size_t)(NKV*HD) * DIMV];
__device__ __align__(1024) __nv_bfloat16 g_woth[(size_t)DIMV * DIMV];
__device__ __align__(1024) __nv_bfloat16 g_wotl[(size_t)DIMV * DIMV];
__device__ __align__(1024) __nv_bfloat16 g_atth[(size_t)TOKENS * DIMV];
__device__ __align__(1024) __nv_bfloat16 g_attl[(size_t)TOKENS * DIMV];

// ================= helpers =================
__device__ __forceinline__ uint32_t smem_u32(const void* p) {
    return (uint32_t)__cvta_generic_to_shared(p);
}
__device__ __forceinline__ void cp16(uint32_t dst, const void* src) {
    asm volatile("cp.async.cg.shared.global [%0], [%1], 16;" :: "r"(dst), "l"(src));
}
__device__ __forceinline__ void cp_commit() {
    asm volatile("cp.async.commit_group;" ::: "memory");
}
__device__ __forceinline__ void cp_wait1() {
    asm volatile("cp.async.wait_group 1;" ::: "memory");
}
__device__ __forceinline__ void cp_wait0() {
    asm volatile("cp.async.wait_group 0;" ::: "memory");
}
__device__ __forceinline__ void ldsm4(uint32_t& r0, uint32_t& r1, uint32_t& r2, uint32_t& r3,
                                      uint32_t addr) {
    asm volatile("ldmatrix.sync.aligned.m8n8.x4.shared.b16 {%0,%1,%2,%3}, [%4];"
                 : "=r"(r0), "=r"(r1), "=r"(r2), "=r"(r3) : "r"(addr));
}
__device__ __forceinline__ void mma16816(float* c, const uint32_t* a, uint32_t b0, uint32_t b1) {
    asm volatile(
        "mma.sync.aligned.m16n8k16.row.col.f32.bf16.bf16.f32 "
        "{%0,%1,%2,%3}, {%4,%5,%6,%7}, {%8,%9}, {%0,%1,%2,%3};"
        : "+f"(c[0]), "+f"(c[1]), "+f"(c[2]), "+f"(c[3])
        : "r"(a[0]), "r"(a[1]), "r"(a[2]), "r"(a[3]), "r"(b0), "r"(b1));
}

// ================= bf16x3 HMMA GEMM: C[M,N] = A[M,K] @ B[N,K]^T =================
// BM=128, BN=128, BK=64, 2-stage cp.async pipeline, 8 warps (2m x 4n), 64x32/warp.
#define BM 128
#define BN 128
#define BK 64
#define LDS_B   144                 // 72 bf16 per smem row (64 data + 8 pad)
#define TILE_B  (128 * LDS_B)       // 18432 bytes per tile
#define STAGE_B (4 * TILE_B)        // Ah, Al, Bh, Bl
#define GEMM_SMEM (2 * STAGE_B)     // 147456

__device__ __forceinline__ void load_stage_async(
    uint32_t sb, int s,
    const __nv_bfloat16* Ah, const __nv_bfloat16* Al,
    const __nv_bfloat16* Bh, const __nv_bfloat16* Bl,
    int K, int k0, int tid)
{
    uint32_t st = sb + s * STAGE_B;
#pragma unroll
    for (int t = 0; t < 4; t++) {
        int c = tid + t * 256;
        int row = c >> 3, chb = (c & 7) << 4;
        size_t go = (size_t)row * K + k0;
        uint32_t dst = st + row * LDS_B + chb;
        cp16(dst,              (const char*)(Ah + go) + chb);
        cp16(dst + TILE_B,     (const char*)(Al + go) + chb);
        cp16(dst + 2 * TILE_B, (const char*)(Bh + go) + chb);
        cp16(dst + 3 * TILE_B, (const char*)(Bl + go) + chb);
    }
}

__global__ void __launch_bounds__(256, 1) gemm_mma(
    const __nv_bfloat16* __restrict__ Ah, const __nv_bfloat16* __restrict__ Al,
    const __nv_bfloat16* __restrict__ Bh, const __nv_bfloat16* __restrict__ Bl,
    float* __restrict__ C, int N, int K)
{
    extern __shared__ char smem[];
    uint32_t sb = smem_u32(smem);
    const int tid = threadIdx.x, wid = tid >> 5, lane = tid & 31;
    const int wm = wid & 1, wn = wid >> 1;      // 2 x 4 warp grid
    const int bm0 = blockIdx.y * BM;
    const int bn0 = blockIdx.x * BN;

    const __nv_bfloat16* pAh = Ah + (size_t)bm0 * K;
    const __nv_bfloat16* pAl = Al + (size_t)bm0 * K;
    const __nv_bfloat16* pBh = Bh + (size_t)bn0 * K;
    const __nv_bfloat16* pBl = Bl + (size_t)bn0 * K;

    float acc[4][4][4];
#pragma unroll
    for (int i = 0; i < 4; i++)
#pragma unroll
        for (int j = 0; j < 4; j++)
#pragma unroll
            for (int r = 0; r < 4; r++) acc[i][j][r] = 0.f;

    const int NIT = K / BK;
    load_stage_async(sb, 0, pAh, pAl, pBh, pBl, K, 0, tid);
    cp_commit();

    // per-lane fragment address components
    const int a_row = wm * 64 + (lane & 15);          // + mi*16
    const int a_col = (lane >> 4) << 3;               // + ks*16
    const int bg = lane >> 3;
    const int b_row = wn * 32 + ((bg >> 1) << 3) + (lane & 7);   // + p*16
    const int b_col = (bg & 1) << 3;                  // + ks*16

    for (int it = 0; it < NIT; ++it) {
        if (it + 1 < NIT) {
            load_stage_async(sb, (it + 1) & 1, pAh, pAl, pBh, pBl, K, (it + 1) * BK, tid);
            cp_commit();
            cp_wait1();
        } else {
            cp_wait0();
        }
        __syncthreads();

        uint32_t st = sb + (it & 1) * STAGE_B;
#pragma unroll
        for (int ks = 0; ks < 4; ks++) {
            uint32_t ah[4][4], al[4][4];
#pragma unroll
            for (int mi = 0; mi < 4; mi++) {
                uint32_t ad = st + (a_row + mi * 16) * LDS_B + (a_col + ks * 16) * 2;
                ldsm4(ah[mi][0], ah[mi][1], ah[mi][2], ah[mi][3], ad);
                ldsm4(al[mi][0], al[mi][1], al[mi][2], al[mi][3], ad + TILE_B);
            }
            uint32_t bh[4][2], bl[4][2];
#pragma unroll
            for (int p = 0; p < 2; p++) {
                uint32_t bd = st + 2 * TILE_B + (b_row + p * 16) * LDS_B + (b_col + ks * 16) * 2;
                ldsm4(bh[2*p][0], bh[2*p][1], bh[2*p+1][0], bh[2*p+1][1], bd);
                ldsm4(bl[2*p][0], bl[2*p][1], bl[2*p+1][0], bl[2*p+1][1], bd + TILE_B);
            }
#pragma unroll
            for (int mi = 0; mi < 4; mi++)
#pragma unroll
                for (int ni = 0; ni < 4; ni++) {
                    mma16816(acc[mi][ni], ah[mi], bh[ni][0], bh[ni][1]);
                    mma16816(acc[mi][ni], ah[mi], bl[ni][0], bl[ni][1]);
                    mma16816(acc[mi][ni], al[mi], bh[ni][0], bh[ni][1]);
                }
        }
        __syncthreads();
    }

    // epilogue: direct fp32 stores
    const int cr = lane >> 2, cc = (lane & 3) << 1;
#pragma unroll
    for (int mi = 0; mi < 4; mi++) {
        int r0 = bm0 + wm * 64 + mi * 16 + cr;
#pragma unroll
        for (int ni = 0; ni < 4; ni++) {
            int col = bn0 + wn * 32 + ni * 8 + cc;
            *(float2*)(C + (size_t)r0 * N + col)       = make_float2(acc[mi][ni][0], acc[mi][ni][1]);
            *(float2*)(C + (size_t)(r0 + 8) * N + col) = make_float2(acc[mi][ni][2], acc[mi][ni][3]);
        }
    }
}

// ================= split fp32 -> bf16 hi/lo =================
__global__ void split_kernel(const float* __restrict__ src,
                             __nv_bfloat16* __restrict__ h,
                             __nv_bfloat16* __restrict__ l, int n4)
{
    int i = blockIdx.x * blockDim.x + threadIdx.x;
    if (i >= n4) return;
    float4 v = ((const float4*)src)[i];
    __nv_bfloat16 h0 = __float2bfloat16(v.x), h1 = __float2bfloat16(v.y);
    __nv_bfloat16 h2 = __float2bfloat16(v.z), h3 = __float2bfloat16(v.w);
    __nv_bfloat16 l0 = __float2bfloat16(v.x - __bfloat162float(h0));
    __nv_bfloat16 l1 = __float2bfloat16(v.y - __bfloat162float(h1));
    __nv_bfloat16 l2 = __float2bfloat16(v.z - __bfloat162float(h2));
    __nv_bfloat16 l3 = __float2bfloat16(v.w - __bfloat162float(h3));
    ((ushort4*)h)[i] = make_ushort4(__bfloat16_as_ushort(h0), __bfloat16_as_ushort(h1),
                                    __bfloat16_as_ushort(h2), __bfloat16_as_ushort(h3));
    ((ushort4*)l)[i] = make_ushort4(__bfloat16_as_ushort(l0), __bfloat16_as_ushort(l1),
                                    __bfloat16_as_ushort(l2), __bfloat16_as_ushort(l3));
}

// ================= transpose + split: w[K,N] -> wT hi/lo [N,K] =================
__global__ void __launch_bounds__(256) tsplit_kernel(
    const float* __restrict__ w, __nv_bfloat16* __restrict__ th,
    __nv_bfloat16* __restrict__ tl, int K, int N)
{
    __shared__ float t[32][33];
    const int n0 = blockIdx.x * 32, k0 = blockIdx.y * 32;
    const int tx = threadIdx.x & 31, ty = threadIdx.x >> 5;
#pragma unroll
    for (int i = 0; i < 32; i += 8)
        t[ty + i][tx] = w[(size_t)(k0 + ty + i) * N + n0 + tx];
    __syncthreads();
#pragma unroll
    for (int i = 0; i < 32; i += 8) {
        float v = t[tx][ty + i];
        __nv_bfloat16 hb = __float2bfloat16(v);
        size_t o = (size_t)(n0 + ty + i) * K + k0 + tx;
        th[o] = hb;
        tl[o] = __float2bfloat16(v - __bfloat162float(hb));
    }
}

// ================= RoPE (in place), layout [B,S,H,HD] ======================
__global__ void rope_kernel(float* __restrict__ t,
                            const float* __restrict__ fc,
                            const float* __restrict__ fs, int nheads, int total)
{
    int idx = blockIdx.x * blockDim.x + threadIdx.x;
    if (idx >= total) return;
    int j = idx & 63;
    int s = (idx / (64 * nheads)) % SEQ;
    float c  = fc[s * 64 + j];
    float sn = fs[s * 64 + j];
    float* p = t + (size_t)idx * 2;
    float re = p[0], im = p[1];
    p[0] = re * c - im * sn;
    p[1] = re * sn + im * c;
}

// ================= Flash attention, fp32, causal, GQA =====================
#define ATTN_SMEM ((128*72*2 + 64*132 + 64*68) * 4)

__global__ void __launch_bounds__(256, 1) attn_kernel(
    const float* __restrict__ Q, const float* __restrict__ K,
    const float* __restrict__ V, float* __restrict__ O)
{
    extern __shared__ float sm[];
    float* Qt = sm;
    float* Kt = Qt + 128 * 72;
    float* Vs = Kt + 128 * 72;
    float* Ps = Vs + 64 * 132;

    const int tid = threadIdx.x;
    const int tx = tid & 15, ty = tid >> 4;
    const int qt = blockIdx.x, h = blockIdx.y, b = blockIdx.z;
    const int q0 = qt * 64;
    const int kvh = h >> 2;

    const float* Qb = Q + (((size_t)b * SEQ) * NH  + h)   * HD;
    const float* Kb = K + (((size_t)b * SEQ) * NKV + kvh) * HD;
    const float* Vb = V + (((size_t)b * SEQ) * NKV + kvh) * HD;

    const float scale = 0.08838834764831845f;

#pragma unroll
    for (int i = tid; i < 64 * 32; i += 256) {
        int r = i >> 5, c4 = (i & 31) << 2;
        float4 qv = *(const float4*)(Qb + (size_t)(q0 + r) * (NH * HD) + c4);
        Qt[(c4 + 0) * 72 + r] = qv.x * scale;
        Qt[(c4 + 1) * 72 + r] = qv.y * scale;
        Qt[(c4 + 2) * 72 + r] = qv.z * scale;
        Qt[(c4 + 3) * 72 + r] = qv.w * scale;
    }

    float acc[4][8];
#pragma unroll
    for (int i = 0; i < 4; i++)
#pragma unroll
        for (int j = 0; j < 8; j++) acc[i][j] = 0.f;
    float mrow[4] = {-1e30f, -1e30f, -1e30f, -1e30f};
    float lrow[4] = {0.f, 0.f, 0.f, 0.f};

    for (int kt = 0; kt <= qt; kt++) {
        const int k0 = kt * 64;
        __syncthreads();
#pragma unroll
        for (int i = tid; i < 64 * 32; i += 256) {
            int r = i >> 5, c4 = (i & 31) << 2;
            float4 kv = *(const float4*)(Kb + (size_t)(k0 + r) * (NKV * HD) + c4);
            Kt[(c4 + 0) * 72 + r] = kv.x;
            Kt[(c4 + 1) * 72 + r] = kv.y;
            Kt[(c4 + 2) * 72 + r] = kv.z;
            Kt[(c4 + 3) * 72 + r] = kv.w;
            float4 vv = *(const float4*)(Vb + (size_t)(k0 + r) * (NKV * HD) + c4);
            *(float4*)(Vs + r * 132 + c4) = vv;
        }
        __syncthreads();

        float s[4][4];
#pragma unroll
        for (int i = 0; i < 4; i++)
#pragma unroll
            for (int j = 0; j < 4; j++) s[i][j] = 0.f;

#pragma unroll 4
        for (int d = 0; d < 128; d++) {
            float4 aa = *(const float4*)(Qt + d * 72 + ty * 4);
            float4 bb = *(const float4*)(Kt + d * 72 + tx * 4);
            float a[4] = {aa.x, aa.y, aa.z, aa.w};
            float bv[4] = {bb.x, bb.y, bb.z, bb.w};
#pragma unroll
            for (int i = 0; i < 4; i++)
#pragma unroll
                for (int j = 0; j < 4; j++) s[i][j] = fmaf(a[i], bv[j], s[i][j]);
        }

        if (kt == qt) {
#pragma unroll
            for (int i = 0; i < 4; i++)
#pragma unroll
                for (int j = 0; j < 4; j++)
                    if ((k0 + tx * 4 + j) > (q0 + ty * 4 + i)) s[i][j] = -1e30f;
        }

#pragma unroll
        for (int i = 0; i < 4; i++) {
            float mx = fmaxf(fmaxf(s[i][0], s[i][1]), fmaxf(s[i][2], s[i][3]));
            mx = fmaxf(mx, __shfl_xor_sync(0xffffffffu, mx, 8));
            mx = fmaxf(mx, __shfl_xor_sync(0xffffffffu, mx, 4));
            mx = fmaxf(mx, __shfl_xor_sync(0xffffffffu, mx, 2));
            mx = fmaxf(mx, __shfl_xor_sync(0xffffffffu, mx, 1));
            float mnew = fmaxf(mrow[i], mx);
            float corr = __expf(mrow[i] - mnew);
            float psum = 0.f;
#pragma unroll
            for (int j = 0; j < 4; j++) {
                float p = __expf(s[i][j] - mnew);
                psum += p;
                Ps[(ty * 4 + i) * 68 + tx * 4 + j] = p;
            }
            psum += __shfl_xor_sync(0xffffffffu, psum, 8);
            psum += __shfl_xor_sync(0xffffffffu, psum, 4);
            psum += __shfl_xor_sync(0xffffffffu, psum, 2);
            psum += __shfl_xor_sync(0xffffffffu, psum, 1);
            lrow[i] = lrow[i] * corr + psum;
            mrow[i] = mnew;
#pragma unroll
            for (int j = 0; j < 8; j++) acc[i][j] *= corr;
        }
        __syncthreads();

#pragma unroll 4
        for (int kk = 0; kk < 64; kk++) {
            float4 v0 = *(const float4*)(Vs + kk * 132 + tx * 8);
            float4 v1 = *(const float4*)(Vs + kk * 132 + tx * 8 + 4);
#pragma unroll
            for (int i = 0; i < 4; i++) {
                float p = Ps[(ty * 4 + i) * 68 + kk];
                acc[i][0] = fmaf(p, v0.x, acc[i][0]);
                acc[i][1] = fmaf(p, v0.y, acc[i][1]);
                acc[i][2] = fmaf(p, v0.z, acc[i][2]);
                acc[i][3] = fmaf(p, v0.w, acc[i][3]);
                acc[i][4] = fmaf(p, v1.x, acc[i][4]);
                acc[i][5] = fmaf(p, v1.y, acc[i][5]);
                acc[i][6] = fmaf(p, v1.z, acc[i][6]);
                acc[i][7] = fmaf(p, v1.w, acc[i][7]);
            }
        }
    }

#pragma unroll
    for (int i = 0; i < 4; i++) {
        float inv = 1.f / lrow[i];
        int row = q0 + ty * 4 + i;
        float4 o0 = make_float4(acc[i][0] * inv, acc[i][1] * inv,
                                acc[i][2] * inv, acc[i][3] * inv);
        float4 o1 = make_float4(acc[i][4] * inv, acc[i][5] * inv,
                                acc[i][6] * inv, acc[i][7] * inv);
        float* dst = O + (((size_t)b * SEQ + row) * NH + h) * HD + tx * 8;
        *(float4*)(dst)     = o0;
        *(float4*)(dst + 4) = o1;
    }
}

// ============================ launch ======================================
extern "C" void kernel_launch(void* const* d_in, const int* in_sizes, int n_in,
                              void* d_out, int out_size)
{
    const float* x  = (const float*)d_in[0];
    const float* wq = (const float*)d_in[1];
    const float* wk = (const float*)d_in[2];
    const float* wv = (const float*)d_in[3];
    const float* wo = (const float*)d_in[4];
    const float* fc = (const float*)d_in[7];
    const float* fs = (const float*)d_in[8];
    float* out = (float*)d_out;
    (void)in_sizes; (void)n_in; (void)out_size;

    float *q, *k, *v, *att;
    cudaGetSymbolAddress((void**)&q,   g_q);
    cudaGetSymbolAddress((void**)&k,   g_k);
    cudaGetSymbolAddress((void**)&v,   g_v);
    cudaGetSymbolAddress((void**)&att, g_att);
    __nv_bfloat16 *xh, *xl, *wqth, *wqtl, *wkth, *wktl, *wvth, *wvtl, *woth, *wotl, *atth, *attl;
    cudaGetSymbolAddress((void**)&xh,   g_xh);
    cudaGetSymbolAddress((void**)&xl,   g_xl);
    cudaGetSymbolAddress((void**)&wqth, g_wqth);
    cudaGetSymbolAddress((void**)&wqtl, g_wqtl);
    cudaGetSymbolAddress((void**)&wkth, g_wkth);
    cudaGetSymbolAddress((void**)&wktl, g_wktl);
    cudaGetSymbolAddress((void**)&wvth, g_wvth);
    cudaGetSymbolAddress((void**)&wvtl, g_wvtl);
    cudaGetSymbolAddress((void**)&woth, g_woth);
    cudaGetSymbolAddress((void**)&wotl, g_wotl);
    cudaGetSymbolAddress((void**)&atth, g_atth);
    cudaGetSymbolAddress((void**)&attl, g_attl);

    cudaFuncSetAttribute(gemm_mma,    cudaFuncAttributeMaxDynamicSharedMemorySize, GEMM_SMEM);
    cudaFuncSetAttribute(attn_kernel, cudaFuncAttributeMaxDynamicSharedMemorySize, ATTN_SMEM);

    // ---- prep: split x, transpose+split weights ----
    const int n4x = TOKENS * DIMV / 4;
    split_kernel<<<n4x / 256, 256>>>(x, xh, xl, n4x);
    tsplit_kernel<<<dim3(DIMV / 32,     DIMV / 32), 256>>>(wq, wqth, wqtl, DIMV, DIMV);
    tsplit_kernel<<<dim3(NKV * HD / 32, DIMV / 32), 256>>>(wk, wkth, wktl, DIMV, NKV * HD);
    tsplit_kernel<<<dim3(NKV * HD / 32, DIMV / 32), 256>>>(wv, wvth, wvtl, DIMV, NKV * HD);
    tsplit_kernel<<<dim3(DIMV / 32,     DIMV / 32), 256>>>(wo, woth, wotl, DIMV, DIMV);

    // ---- projections on HMMA (bf16x3) ----
    gemm_mma<<<dim3((NH*HD)/BN,  TOKENS/BM), 256, GEMM_SMEM>>>(xh, xl, wqth, wqtl, q, NH*HD,  DIMV);
    gemm_mma<<<dim3((NKV*HD)/BN, TOKENS/BM), 256, GEMM_SMEM>>>(xh, xl, wkth, wktl, k, NKV*HD, DIMV);
    gemm_mma<<<dim3((NKV*HD)/BN, TOKENS/BM), 256, GEMM_SMEM>>>(xh, xl, wvth, wvtl, v, NKV*HD, DIMV);

    // ---- RoPE ----
    {
        int tq = BATCH_ * SEQ * NH * 64;
        int tk = BATCH_ * SEQ * NKV * 64;
        rope_kernel<<<(tq + 255) / 256, 256>>>(q, fc, fs, NH,  tq);
        rope_kernel<<<(tk + 255) / 256, 256>>>(k, fc, fs, NKV, tk);
    }

    // ---- attention (fp32) ----
    attn_kernel<<<dim3(SEQ / 64, NH, BATCH_), 256, ATTN_SMEM>>>(q, k, v, att);

    // ---- output projection on HMMA ----
    const int n4a = TOKENS * DIMV / 4;
    split_kernel<<<n4a / 256, 256>>>(att, atth, attl, n4a);
    gemm_mma<<<dim3(DIMV/BN, TOKENS/BM), 256, GEMM_SMEM>>>(atth, attl, woth, wotl, out, DIMV, DIMV);
}

// round 4
// speedup vs baseline: 3.2450x; 2.9039x over previous
#include <cuda_runtime.h>
#include <cuda_bf16.h>
#include <math.h>
#include <stdint.h>

#define BATCH_ 2
#define SEQ    2048
#define DIMV   4096
#define NH     32
#define NKV    8
#define HD     128
#define TOKENS (BATCH_*SEQ)   // 4096

// ---------------- scratch (no cudaMalloc allowed) ----------------
__device__ __align__(1024) float g_q  [(size_t)TOKENS * NH  * HD];
__device__ __align__(1024) float g_k  [(size_t)TOKENS * NKV * HD];
__device__ __align__(1024) float g_v  [(size_t)TOKENS * NKV * HD];

__device__ __align__(1024) __nv_bfloat16 g_xh  [(size_t)TOKENS * DIMV];
__device__ __align__(1024) __nv_bfloat16 g_xl  [(size_t)TOKENS * DIMV];
__device__ __align__(1024) __nv_bfloat16 g_wqth[(size_t)DIMV * DIMV];
__device__ __align__(1024) __nv_bfloat16 g_wqtl[(size_t)DIMV * DIMV];
__device__ __align__(1024) __nv_bfloat16 g_wkth[(size_t)(NKV*HD) * DIMV];
__device__ __align__(1024) __nv_bfloat16 g_wktl[(size_t)(NKV*HD) * DIMV];
__device__ __align__(1024) __nv_bfloat16 g_wvth[(size_t)(NKV*HD) * DIMV];
__device__ __align__(1024) __nv_bfloat16 g_wvtl[(size_t)(NKV*HD) * DIMV];
__device__ __align__(1024) __nv_bfloat16 g_woth[(size_t)DIMV * DIMV];
__device__ __align__(1024) __nv_bfloat16 g_wotl[(size_t)DIMV * DIMV];
__device__ __align__(1024) __nv_bfloat16 g_atth[(size_t)TOKENS * DIMV];
__device__ __align__(1024) __nv_bfloat16 g_attl[(size_t)TOKENS * DIMV];

__device__ __align__(1024) __nv_bfloat16 g_qh[(size_t)TOKENS * NH  * HD];
__device__ __align__(1024) __nv_bfloat16 g_ql[(size_t)TOKENS * NH  * HD];
__device__ __align__(1024) __nv_bfloat16 g_kh[(size_t)TOKENS * NKV * HD];
__device__ __align__(1024) __nv_bfloat16 g_kl[(size_t)TOKENS * NKV * HD];
__device__ __align__(1024) __nv_bfloat16 g_vh[(size_t)TOKENS * NKV * HD];
__device__ __align__(1024) __nv_bfloat16 g_vl[(size_t)TOKENS * NKV * HD];

// ================= helpers =================
__device__ __forceinline__ uint32_t smem_u32(const void* p) {
    return (uint32_t)__cvta_generic_to_shared(p);
}
__device__ __forceinline__ void cp16(uint32_t dst, const void* src) {
    asm volatile("cp.async.cg.shared.global [%0], [%1], 16;" :: "r"(dst), "l"(src));
}
__device__ __forceinline__ void cp_commit() {
    asm volatile("cp.async.commit_group;" ::: "memory");
}
__device__ __forceinline__ void cp_wait1() {
    asm volatile("cp.async.wait_group 1;" ::: "memory");
}
__device__ __forceinline__ void cp_wait0() {
    asm volatile("cp.async.wait_group 0;" ::: "memory");
}
__device__ __forceinline__ void ldsm4(uint32_t& r0, uint32_t& r1, uint32_t& r2, uint32_t& r3,
                                      uint32_t addr) {
    asm volatile("ldmatrix.sync.aligned.m8n8.x4.shared.b16 {%0,%1,%2,%3}, [%4];"
                 : "=r"(r0), "=r"(r1), "=r"(r2), "=r"(r3) : "r"(addr));
}
__device__ __forceinline__ void ldsm4t(uint32_t& r0, uint32_t& r1, uint32_t& r2, uint32_t& r3,
                                       uint32_t addr) {
    asm volatile("ldmatrix.sync.aligned.m8n8.x4.trans.shared.b16 {%0,%1,%2,%3}, [%4];"
                 : "=r"(r0), "=r"(r1), "=r"(r2), "=r"(r3) : "r"(addr));
}
__device__ __forceinline__ void mma16816(float* c, const uint32_t* a, uint32_t b0, uint32_t b1) {
    asm volatile(
        "mma.sync.aligned.m16n8k16.row.col.f32.bf16.bf16.f32 "
        "{%0,%1,%2,%3}, {%4,%5,%6,%7}, {%8,%9}, {%0,%1,%2,%3};"
        : "+f"(c[0]), "+f"(c[1]), "+f"(c[2]), "+f"(c[3])
        : "r"(a[0]), "r"(a[1]), "r"(a[2]), "r"(a[3]), "r"(b0), "r"(b1));
}
__device__ __forceinline__ uint32_t packbf(float a, float b) {
    __nv_bfloat162 t = __floats2bfloat162_rn(a, b);
    return *reinterpret_cast<uint32_t*>(&t);
}

// ================= bf16x3 HMMA GEMM (unchanged from R3) =================
#define BM 128
#define BN 128
#define BK 64
#define LDS_B   144
#define TILE_B  (128 * LDS_B)
#define STAGE_B (4 * TILE_B)
#define GEMM_SMEM (2 * STAGE_B)

__device__ __forceinline__ void load_stage_async(
    uint32_t sb, int s,
    const __nv_bfloat16* Ah, const __nv_bfloat16* Al,
    const __nv_bfloat16* Bh, const __nv_bfloat16* Bl,
    int K, int k0, int tid)
{
    uint32_t st = sb + s * STAGE_B;
#pragma unroll
    for (int t = 0; t < 4; t++) {
        int c = tid + t * 256;
        int row = c >> 3, chb = (c & 7) << 4;
        size_t go = (size_t)row * K + k0;
        uint32_t dst = st + row * LDS_B + chb;
        cp16(dst,              (const char*)(Ah + go) + chb);
        cp16(dst + TILE_B,     (const char*)(Al + go) + chb);
        cp16(dst + 2 * TILE_B, (const char*)(Bh + go) + chb);
        cp16(dst + 3 * TILE_B, (const char*)(Bl + go) + chb);
    }
}

__global__ void __launch_bounds__(256, 1) gemm_mma(
    const __nv_bfloat16* __restrict__ Ah, const __nv_bfloat16* __restrict__ Al,
    const __nv_bfloat16* __restrict__ Bh, const __nv_bfloat16* __restrict__ Bl,
    float* __restrict__ C, int N, int K)
{
    extern __shared__ char smem[];
    uint32_t sb = smem_u32(smem);
    const int tid = threadIdx.x, wid = tid >> 5, lane = tid & 31;
    const int wm = wid & 1, wn = wid >> 1;
    const int bm0 = blockIdx.y * BM;
    const int bn0 = blockIdx.x * BN;

    const __nv_bfloat16* pAh = Ah + (size_t)bm0 * K;
    const __nv_bfloat16* pAl = Al + (size_t)bm0 * K;
    const __nv_bfloat16* pBh = Bh + (size_t)bn0 * K;
    const __nv_bfloat16* pBl = Bl + (size_t)bn0 * K;

    float acc[4][4][4];
#pragma unroll
    for (int i = 0; i < 4; i++)
#pragma unroll
        for (int j = 0; j < 4; j++)
#pragma unroll
            for (int r = 0; r < 4; r++) acc[i][j][r] = 0.f;

    const int NIT = K / BK;
    load_stage_async(sb, 0, pAh, pAl, pBh, pBl, K, 0, tid);
    cp_commit();

    const int a_row = wm * 64 + (lane & 15);
    const int a_col = (lane >> 4) << 3;
    const int bg = lane >> 3;
    const int b_row = wn * 32 + ((bg >> 1) << 3) + (lane & 7);
    const int b_col = (bg & 1) << 3;

    for (int it = 0; it < NIT; ++it) {
        if (it + 1 < NIT) {
            load_stage_async(sb, (it + 1) & 1, pAh, pAl, pBh, pBl, K, (it + 1) * BK, tid);
            cp_commit();
            cp_wait1();
        } else {
            cp_wait0();
        }
        __syncthreads();

        uint32_t st = sb + (it & 1) * STAGE_B;
#pragma unroll
        for (int ks = 0; ks < 4; ks++) {
            uint32_t ah[4][4], al[4][4];
#pragma unroll
            for (int mi = 0; mi < 4; mi++) {
                uint32_t ad = st + (a_row + mi * 16) * LDS_B + (a_col + ks * 16) * 2;
                ldsm4(ah[mi][0], ah[mi][1], ah[mi][2], ah[mi][3], ad);
                ldsm4(al[mi][0], al[mi][1], al[mi][2], al[mi][3], ad + TILE_B);
            }
            uint32_t bh[4][2], bl[4][2];
#pragma unroll
            for (int p = 0; p < 2; p++) {
                uint32_t bd = st + 2 * TILE_B + (b_row + p * 16) * LDS_B + (b_col + ks * 16) * 2;
                ldsm4(bh[2*p][0], bh[2*p][1], bh[2*p+1][0], bh[2*p+1][1], bd);
                ldsm4(bl[2*p][0], bl[2*p][1], bl[2*p+1][0], bl[2*p+1][1], bd + TILE_B);
            }
#pragma unroll
            for (int mi = 0; mi < 4; mi++)
#pragma unroll
                for (int ni = 0; ni < 4; ni++) {
                    mma16816(acc[mi][ni], ah[mi], bh[ni][0], bh[ni][1]);
                    mma16816(acc[mi][ni], ah[mi], bl[ni][0], bl[ni][1]);
                    mma16816(acc[mi][ni], al[mi], bh[ni][0], bh[ni][1]);
                }
        }
        __syncthreads();
    }

    const int cr = lane >> 2, cc = (lane & 3) << 1;
#pragma unroll
    for (int mi = 0; mi < 4; mi++) {
        int r0 = bm0 + wm * 64 + mi * 16 + cr;
#pragma unroll
        for (int ni = 0; ni < 4; ni++) {
            int col = bn0 + wn * 32 + ni * 8 + cc;
            *(float2*)(C + (size_t)r0 * N + col)       = make_float2(acc[mi][ni][0], acc[mi][ni][1]);
            *(float2*)(C + (size_t)(r0 + 8) * N + col) = make_float2(acc[mi][ni][2], acc[mi][ni][3]);
        }
    }
}

// ================= split fp32 -> bf16 hi/lo =================
__global__ void split_kernel(const float* __restrict__ src,
                             __nv_bfloat16* __restrict__ h,
                             __nv_bfloat16* __restrict__ l, int n4)
{
    int i = blockIdx.x * blockDim.x + threadIdx.x;
    if (i >= n4) return;
    float4 v = ((const float4*)src)[i];
    __nv_bfloat16 h0 = __float2bfloat16(v.x), h1 = __float2bfloat16(v.y);
    __nv_bfloat16 h2 = __float2bfloat16(v.z), h3 = __float2bfloat16(v.w);
    __nv_bfloat16 l0 = __float2bfloat16(v.x - __bfloat162float(h0));
    __nv_bfloat16 l1 = __float2bfloat16(v.y - __bfloat162float(h1));
    __nv_bfloat16 l2 = __float2bfloat16(v.z - __bfloat162float(h2));
    __nv_bfloat16 l3 = __float2bfloat16(v.w - __bfloat162float(h3));
    ((ushort4*)h)[i] = make_ushort4(__bfloat16_as_ushort(h0), __bfloat16_as_ushort(h1),
                                    __bfloat16_as_ushort(h2), __bfloat16_as_ushort(h3));
    ((ushort4*)l)[i] = make_ushort4(__bfloat16_as_ushort(l0), __bfloat16_as_ushort(l1),
                                    __bfloat16_as_ushort(l2), __bfloat16_as_ushort(l3));
}

// ================= transpose + split: w[K,N] -> wT hi/lo [N,K] =================
__global__ void __launch_bounds__(256) tsplit_kernel(
    const float* __restrict__ w, __nv_bfloat16* __restrict__ th,
    __nv_bfloat16* __restrict__ tl, int K, int N)
{
    __shared__ float t[32][33];
    const int n0 = blockIdx.x * 32, k0 = blockIdx.y * 32;
    const int tx = threadIdx.x & 31, ty = threadIdx.x >> 5;
#pragma unroll
    for (int i = 0; i < 32; i += 8)
        t[ty + i][tx] = w[(size_t)(k0 + ty + i) * N + n0 + tx];
    __syncthreads();
#pragma unroll
    for (int i = 0; i < 32; i += 8) {
        float v = t[tx][ty + i];
        __nv_bfloat16 hb = __float2bfloat16(v);
        size_t o = (size_t)(n0 + ty + i) * K + k0 + tx;
        th[o] = hb;
        tl[o] = __float2bfloat16(v - __bfloat162float(hb));
    }
}

// ========== fused RoPE + (optional scale) + bf16 hi/lo split ==========
__global__ void rope_split(const float* __restrict__ t,
                           const float* __restrict__ fc, const float* __restrict__ fs,
                           __nv_bfloat16* __restrict__ oh, __nv_bfloat16* __restrict__ ol,
                           int nheads, int total, float scl)
{
    int idx = blockIdx.x * blockDim.x + threadIdx.x;
    if (idx >= total) return;
    int j = idx & 63;
    int s = (idx / (64 * nheads)) % SEQ;
    float c = fc[s * 64 + j], sn = fs[s * 64 + j];
    float2 v = ((const float2*)t)[idx];
    float re = (v.x * c - v.y * sn) * scl;
    float im = (v.x * sn + v.y * c) * scl;
    __nv_bfloat16 rh = __float2bfloat16(re), ih = __float2bfloat16(im);
    __nv_bfloat162 hv; hv.x = rh; hv.y = ih;
    ((__nv_bfloat162*)oh)[idx] = hv;
    __nv_bfloat162 lv;
    lv.x = __float2bfloat16(re - __bfloat162float(rh));
    lv.y = __float2bfloat16(im - __bfloat162float(ih));
    ((__nv_bfloat162*)ol)[idx] = lv;
}

// ================= HMMA bf16x3 flash attention =================
// CTA: (q-tile 128, head, batch). 8 warps x 16 q-rows. KV tiles of 64 keys.
#define AT_LDS 272                         // bytes per smem row (128 bf16 + pad)
#define AT_QT  (128 * AT_LDS)              // 34816
#define AT_KVT (64 * AT_LDS)               // 17408
#define AT_STG (4 * AT_KVT)                // Kh, Kl, Vh, Vl
#define ATTN_SMEM (2 * AT_QT + 2 * AT_STG) // 208896

__global__ void __launch_bounds__(256, 1) attn_mma(
    const __nv_bfloat16* __restrict__ Qh, const __nv_bfloat16* __restrict__ Ql,
    const __nv_bfloat16* __restrict__ Kh, const __nv_bfloat16* __restrict__ Kl,
    const __nv_bfloat16* __restrict__ Vh, const __nv_bfloat16* __restrict__ Vl,
    __nv_bfloat16* __restrict__ Oh, __nv_bfloat16* __restrict__ Ol)
{
    extern __shared__ char sm_[];
    uint32_t sb = smem_u32(sm_);
    const int tid = threadIdx.x, wid = tid >> 5, lane = tid & 31;
    const int qt = blockIdx.x, h = blockIdx.y, b = blockIdx.z;
    const int q0 = qt * 128, kvh = h >> 2;
    const int nkv = 2 * qt + 2;

    const char* Qhg = (const char*)(Qh + ((size_t)(b * SEQ + q0) * NH + h) * HD);
    const char* Qlg = (const char*)(Ql + ((size_t)(b * SEQ + q0) * NH + h) * HD);
    const char* Khg = (const char*)(Kh + ((size_t)(b * SEQ) * NKV + kvh) * HD);
    const char* Klg = (const char*)(Kl + ((size_t)(b * SEQ) * NKV + kvh) * HD);
    const char* Vhg = (const char*)(Vh + ((size_t)(b * SEQ) * NKV + kvh) * HD);
    const char* Vlg = (const char*)(Vl + ((size_t)(b * SEQ) * NKV + kvh) * HD);

    // Q tile loads (group together with KV stage 0)
    for (int c = tid; c < 128 * 16; c += 256) {
        int r = c >> 4, ch = (c & 15) << 4;
        cp16(sb + r * AT_LDS + ch,         Qhg + (size_t)r * 8192 + ch);
        cp16(sb + AT_QT + r * AT_LDS + ch, Qlg + (size_t)r * 8192 + ch);
    }
    auto load_kv = [&](int kt, int s) {
        uint32_t st = sb + 2 * AT_QT + s * AT_STG;
        size_t gof = (size_t)kt * 64 * 2048;
        for (int c = tid; c < 64 * 16; c += 256) {
            int r = c >> 4, ch = (c & 15) << 4;
            uint32_t d = st + r * AT_LDS + ch;
            size_t g = gof + (size_t)r * 2048 + ch;
            cp16(d,              Khg + g);
            cp16(d + AT_KVT,     Klg + g);
            cp16(d + 2 * AT_KVT, Vhg + g);
            cp16(d + 3 * AT_KVT, Vlg + g);
        }
    };
    load_kv(0, 0);
    cp_commit();

    uint32_t qfh[8][4], qfl[8][4];
    float oacc[16][4];
#pragma unroll
    for (int i = 0; i < 16; i++)
#pragma unroll
        for (int r = 0; r < 4; r++) oacc[i][r] = 0.f;
    float mrow0 = -1e30f, mrow1 = -1e30f, lrow0 = 0.f, lrow1 = 0.f;

    const int bg = lane >> 3;
    const int kb_row = ((bg >> 1) << 3) + (lane & 7);
    const int kb_col = (bg & 1) << 3;

    for (int kt = 0; kt < nkv; kt++) {
        if (kt + 1 < nkv) { load_kv(kt + 1, (kt + 1) & 1); cp_commit(); cp_wait1(); }
        else             { cp_wait0(); }
        __syncthreads();

        if (kt == 0) {   // Q frags -> registers (Q smem not reused after)
            uint32_t qa = sb + (wid * 16 + (lane & 15)) * AT_LDS + (((lane >> 4) << 3)) * 2;
#pragma unroll
            for (int kc = 0; kc < 8; kc++) {
                ldsm4(qfh[kc][0], qfh[kc][1], qfh[kc][2], qfh[kc][3], qa + kc * 32);
                ldsm4(qfl[kc][0], qfl[kc][1], qfl[kc][2], qfl[kc][3], qa + kc * 32 + AT_QT);
            }
        }
        uint32_t st = sb + 2 * AT_QT + (kt & 1) * AT_STG;

        // ---- S = Q K^T, bf16x3 ----
        float sacc[8][4];
#pragma unroll
        for (int i = 0; i < 8; i++)
#pragma unroll
            for (int r = 0; r < 4; r++) sacc[i][r] = 0.f;

#pragma unroll
        for (int kc = 0; kc < 8; kc++) {
#pragma unroll
            for (int pr = 0; pr < 4; pr++) {
                uint32_t bd = st + (pr * 16 + kb_row) * AT_LDS + (kc * 16 + kb_col) * 2;
                uint32_t k0r, k1r, k2r, k3r, l0r, l1r, l2r, l3r;
                ldsm4(k0r, k1r, k2r, k3r, bd);
                ldsm4(l0r, l1r, l2r, l3r, bd + AT_KVT);
                mma16816(sacc[2*pr],   qfh[kc], k0r, k1r);
                mma16816(sacc[2*pr],   qfh[kc], l0r, l1r);
                mma16816(sacc[2*pr],   qfl[kc], k0r, k1r);
                mma16816(sacc[2*pr+1], qfh[kc], k2r, k3r);
                mma16816(sacc[2*pr+1], qfh[kc], l2r, l3r);
                mma16816(sacc[2*pr+1], qfl[kc], k2r, k3r);
            }
        }

        // ---- causal mask (only last two kv tiles can clip) ----
        const int k0g = kt * 64;
        const int rlo = q0 + wid * 16 + (lane >> 2);
        if (kt >= nkv - 2) {
#pragma unroll
            for (int nj = 0; nj < 8; nj++) {
                int key = k0g + nj * 8 + ((lane & 3) << 1);
                if (key     > rlo)     sacc[nj][0] = -1e30f;
                if (key + 1 > rlo)     sacc[nj][1] = -1e30f;
                if (key     > rlo + 8) sacc[nj][2] = -1e30f;
                if (key + 1 > rlo + 8) sacc[nj][3] = -1e30f;
            }
        }

        // ---- online softmax (rows lane>>2 and +8) ----
        float mx0 = -1e30f, mx1 = -1e30f;
#pragma unroll
        for (int nj = 0; nj < 8; nj++) {
            mx0 = fmaxf(mx0, fmaxf(sacc[nj][0], sacc[nj][1]));
            mx1 = fmaxf(mx1, fmaxf(sacc[nj][2], sacc[nj][3]));
        }
        mx0 = fmaxf(mx0, __shfl_xor_sync(0xffffffffu, mx0, 1));
        mx0 = fmaxf(mx0, __shfl_xor_sync(0xffffffffu, mx0, 2));
        mx1 = fmaxf(mx1, __shfl_xor_sync(0xffffffffu, mx1, 1));
        mx1 = fmaxf(mx1, __shfl_xor_sync(0xffffffffu, mx1, 2));
        float mn0 = fmaxf(mrow0, mx0), mn1 = fmaxf(mrow1, mx1);
        float cr0 = __expf(mrow0 - mn0), cr1 = __expf(mrow1 - mn1);
        mrow0 = mn0; mrow1 = mn1;
        float sum0 = 0.f, sum1 = 0.f;
#pragma unroll
        for (int nj = 0; nj < 8; nj++) {
            float p0 = __expf(sacc[nj][0] - mn0); sacc[nj][0] = p0; sum0 += p0;
            float p1 = __expf(sacc[nj][1] - mn0); sacc[nj][1] = p1; sum0 += p1;
            float p2 = __expf(sacc[nj][2] - mn1); sacc[nj][2] = p2; sum1 += p2;
            float p3 = __expf(sacc[nj][3] - mn1); sacc[nj][3] = p3; sum1 += p3;
        }
        sum0 += __shfl_xor_sync(0xffffffffu, sum0, 1);
        sum0 += __shfl_xor_sync(0xffffffffu, sum0, 2);
        sum1 += __shfl_xor_sync(0xffffffffu, sum1, 1);
        sum1 += __shfl_xor_sync(0xffffffffu, sum1, 2);
        lrow0 = lrow0 * cr0 + sum0;
        lrow1 = lrow1 * cr1 + sum1;
#pragma unroll
        for (int nj = 0; nj < 16; nj++) {
            oacc[nj][0] *= cr0; oacc[nj][1] *= cr0;
            oacc[nj][2] *= cr1; oacc[nj][3] *= cr1;
        }

        // ---- O += P V, bf16x3 (P frags repacked from sacc) ----
#pragma unroll
        for (int kc = 0; kc < 4; kc++) {
            float p00 = sacc[2*kc][0],   p01 = sacc[2*kc][1];
            float p02 = sacc[2*kc][2],   p03 = sacc[2*kc][3];
            float p10 = sacc[2*kc+1][0], p11 = sacc[2*kc+1][1];
            float p12 = sacc[2*kc+1][2], p13 = sacc[2*kc+1][3];
            uint32_t pah[4], pal[4];
            pah[0] = packbf(p00, p01);  pah[1] = packbf(p02, p03);
            pah[2] = packbf(p10, p11);  pah[3] = packbf(p12, p13);
            {
                __nv_bfloat162* t;
                t = (__nv_bfloat162*)&pah[0];
                pal[0] = packbf(p00 - __bfloat162float(t->x), p01 - __bfloat162float(t->y));
                t = (__nv_bfloat162*)&pah[1];
                pal[1] = packbf(p02 - __bfloat162float(t->x), p03 - __bfloat162float(t->y));
                t = (__nv_bfloat162*)&pah[2];
                pal[2] = packbf(p10 - __bfloat162float(t->x), p11 - __bfloat162float(t->y));
                t = (__nv_bfloat162*)&pah[3];
                pal[3] = packbf(p12 - __bfloat162float(t->x), p13 - __bfloat162float(t->y));
            }
            uint32_t vrow = st + 2 * AT_KVT + (kc * 16 + (lane & 15)) * AT_LDS
                          + (((lane >> 4) << 3)) * 2;
#pragma unroll
            for (int g = 0; g < 8; g++) {
                uint32_t v0, v1, v2, v3, w0, w1, w2, w3;
                ldsm4t(v0, v1, v2, v3, vrow + g * 32);
                ldsm4t(w0, w1, w2, w3, vrow + g * 32 + AT_KVT);
                mma16816(oacc[2*g],   pah, v0, v1);
                mma16816(oacc[2*g],   pal, v0, v1);
                mma16816(oacc[2*g],   pah, w0, w1);
                mma16816(oacc[2*g+1], pah, v2, v3);
                mma16816(oacc[2*g+1], pal, v2, v3);
                mma16816(oacc[2*g+1], pah, w2, w3);
            }
        }
        __syncthreads();
    }

    // ---- epilogue: normalize, split to bf16 hi/lo, store ----
    float inv0 = 1.f / lrow0, inv1 = 1.f / lrow1;
    const int rlo = q0 + wid * 16 + (lane >> 2);
    size_t base_lo = ((size_t)(b * SEQ + rlo) * NH + h) * HD + ((lane & 3) << 1);
    size_t base_hi = base_lo + (size_t)8 * NH * HD;
#pragma unroll
    for (int nj = 0; nj < 16; nj++) {
        float a0 = oacc[nj][0] * inv0, a1 = oacc[nj][1] * inv0;
        float a2 = oacc[nj][2] * inv1, a3 = oacc[nj][3] * inv1;
        __nv_bfloat162 h0; h0.x = __float2bfloat16(a0); h0.y = __float2bfloat16(a1);
        __nv_bfloat162 l0;
        l0.x = __float2bfloat16(a0 - __bfloat162float(h0.x));
        l0.y = __float2bfloat16(a1 - __bfloat162float(h0.y));
        __nv_bfloat162 h1; h1.x = __float2bfloat16(a2); h1.y = __float2bfloat16(a3);
        __nv_bfloat162 l1;
        l1.x = __float2bfloat16(a2 - __bfloat162float(h1.x));
        l1.y = __float2bfloat16(a3 - __bfloat162float(h1.y));
        *(__nv_bfloat162*)(Oh + base_lo + nj * 8) = h0;
        *(__nv_bfloat162*)(Ol + base_lo + nj * 8) = l0;
        *(__nv_bfloat162*)(Oh + base_hi + nj * 8) = h1;
        *(__nv_bfloat162*)(Ol + base_hi + nj * 8) = l1;
    }
}

// ============================ launch ======================================
extern "C" void kernel_launch(void* const* d_in, const int* in_sizes, int n_in,
                              void* d_out, int out_size)
{
    const float* x  = (const float*)d_in[0];
    const float* wq = (const float*)d_in[1];
    const float* wk = (const float*)d_in[2];
    const float* wv = (const float*)d_in[3];
    const float* wo = (const float*)d_in[4];
    const float* fc = (const float*)d_in[7];
    const float* fs = (const float*)d_in[8];
    float* out = (float*)d_out;
    (void)in_sizes; (void)n_in; (void)out_size;

    float *q, *k, *v;
    cudaGetSymbolAddress((void**)&q, g_q);
    cudaGetSymbolAddress((void**)&k, g_k);
    cudaGetSymbolAddress((void**)&v, g_v);
    __nv_bfloat16 *xh, *xl, *wqth, *wqtl, *wkth, *wktl, *wvth, *wvtl, *woth, *wotl, *atth, *attl;
    __nv_bfloat16 *qh, *ql, *kh, *kl, *vh, *vl;
    cudaGetSymbolAddress((void**)&xh,   g_xh);
    cudaGetSymbolAddress((void**)&xl,   g_xl);
    cudaGetSymbolAddress((void**)&wqth, g_wqth);
    cudaGetSymbolAddress((void**)&wqtl, g_wqtl);
    cudaGetSymbolAddress((void**)&wkth, g_wkth);
    cudaGetSymbolAddress((void**)&wktl, g_wktl);
    cudaGetSymbolAddress((void**)&wvth, g_wvth);
    cudaGetSymbolAddress((void**)&wvtl, g_wvtl);
    cudaGetSymbolAddress((void**)&woth, g_woth);
    cudaGetSymbolAddress((void**)&wotl, g_wotl);
    cudaGetSymbolAddress((void**)&atth, g_atth);
    cudaGetSymbolAddress((void**)&attl, g_attl);
    cudaGetSymbolAddress((void**)&qh,   g_qh);
    cudaGetSymbolAddress((void**)&ql,   g_ql);
    cudaGetSymbolAddress((void**)&kh,   g_kh);
    cudaGetSymbolAddress((void**)&kl,   g_kl);
    cudaGetSymbolAddress((void**)&vh,   g_vh);
    cudaGetSymbolAddress((void**)&vl,   g_vl);

    cudaFuncSetAttribute(gemm_mma, cudaFuncAttributeMaxDynamicSharedMemorySize, GEMM_SMEM);
    cudaFuncSetAttribute(attn_mma, cudaFuncAttributeMaxDynamicSharedMemorySize, ATTN_SMEM);

    // ---- prep: split x, transpose+split weights ----
    const int n4x = TOKENS * DIMV / 4;
    split_kernel<<<n4x / 256, 256>>>(x, xh, xl, n4x);
    tsplit_kernel<<<dim3(DIMV / 32,     DIMV / 32), 256>>>(wq, wqth, wqtl, DIMV, DIMV);
    tsplit_kernel<<<dim3(NKV * HD / 32, DIMV / 32), 256>>>(wk, wkth, wktl, DIMV, NKV * HD);
    tsplit_kernel<<<dim3(NKV * HD / 32, DIMV / 32), 256>>>(wv, wvth, wvtl, DIMV, NKV * HD);
    tsplit_kernel<<<dim3(DIMV / 32,     DIMV / 32), 256>>>(wo, woth, wotl, DIMV, DIMV);

    // ---- projections on HMMA (bf16x3) ----
    gemm_mma<<<dim3((NH*HD)/BN,  TOKENS/BM), 256, GEMM_SMEM>>>(xh, xl, wqth, wqtl, q, NH*HD,  DIMV);
    gemm_mma<<<dim3((NKV*HD)/BN, TOKENS/BM), 256, GEMM_SMEM>>>(xh, xl, wkth, wktl, k, NKV*HD, DIMV);
    gemm_mma<<<dim3((NKV*HD)/BN, TOKENS/BM), 256, GEMM_SMEM>>>(xh, xl, wvth, wvtl, v, NKV*HD, DIMV);

    // ---- fused RoPE + scale + split; plain split for V ----
    {
        const float scale = 0.08838834764831845f;  // 1/sqrt(128)
        int tq = TOKENS * NH * 64;
        int tk = TOKENS * NKV * 64;
        rope_split<<<tq / 256, 256>>>(q, fc, fs, qh, ql, NH,  tq, scale);
        rope_split<<<tk / 256, 256>>>(k, fc, fs, kh, kl, NKV, tk, 1.0f);
        split_kernel<<<(TOKENS * NKV * HD / 4) / 256, 256>>>(v, vh, vl, TOKENS * NKV * HD / 4);
    }

    // ---- flash attention on HMMA (writes bf16 hi/lo directly) ----
    attn_mma<<<dim3(SEQ / 128, NH, BATCH_), 256, ATTN_SMEM>>>(qh, ql, kh, kl, vh, vl, atth, attl);

    // ---- output projection on HMMA ----
    gemm_mma<<<dim3(DIMV/BN, TOKENS/BM), 256, GEMM_SMEM>>>(atth, attl, woth, wotl, out, DIMV, DIMV);
}

// round 5
// speedup vs baseline: 7.2458x; 2.2329x over previous
#include <cuda_runtime.h>
#include <cuda_fp16.h>
#include <math.h>
#include <stdint.h>

#define BATCH_ 2
#define SEQ    2048
#define DIMV   4096
#define NH     32
#define NKV    8
#define HD     128
#define TOKENS (BATCH_*SEQ)   // 4096

// ---------------- scratch (no cudaMalloc allowed) ----------------
__device__ __align__(1024) float  g_q [(size_t)TOKENS * NH  * HD];   // fp32 pre-rope
__device__ __align__(1024) float  g_k [(size_t)TOKENS * NKV * HD];
__device__ __align__(1024) __half g_xh [(size_t)TOKENS * DIMV];
__device__ __align__(1024) __half g_wqt[(size_t)DIMV * DIMV];
__device__ __align__(1024) __half g_wkt[(size_t)(NKV*HD) * DIMV];
__device__ __align__(1024) __half g_wvt[(size_t)(NKV*HD) * DIMV];
__device__ __align__(1024) __half g_wot[(size_t)DIMV * DIMV];
__device__ __align__(1024) __half g_att[(size_t)TOKENS * DIMV];
__device__ __align__(1024) __half g_qh [(size_t)TOKENS * NH  * HD];
__device__ __align__(1024) __half g_kh [(size_t)TOKENS * NKV * HD];
__device__ __align__(1024) __half g_vh [(size_t)TOKENS * NKV * HD];

// ================= helpers =================
__device__ __forceinline__ uint32_t smem_u32(const void* p) {
    return (uint32_t)__cvta_generic_to_shared(p);
}
__device__ __forceinline__ void cp16(uint32_t dst, const void* src) {
    asm volatile("cp.async.cg.shared.global [%0], [%1], 16;" :: "r"(dst), "l"(src));
}
__device__ __forceinline__ void cp_commit() {
    asm volatile("cp.async.commit_group;" ::: "memory");
}
__device__ __forceinline__ void cp_wait2() {
    asm volatile("cp.async.wait_group 2;" ::: "memory");
}
__device__ __forceinline__ void cp_wait1() {
    asm volatile("cp.async.wait_group 1;" ::: "memory");
}
__device__ __forceinline__ void cp_wait0() {
    asm volatile("cp.async.wait_group 0;" ::: "memory");
}
__device__ __forceinline__ void ldsm4(uint32_t& r0, uint32_t& r1, uint32_t& r2, uint32_t& r3,
                                      uint32_t addr) {
    asm volatile("ldmatrix.sync.aligned.m8n8.x4.shared.b16 {%0,%1,%2,%3}, [%4];"
                 : "=r"(r0), "=r"(r1), "=r"(r2), "=r"(r3) : "r"(addr));
}
__device__ __forceinline__ void ldsm4t(uint32_t& r0, uint32_t& r1, uint32_t& r2, uint32_t& r3,
                                       uint32_t addr) {
    asm volatile("ldmatrix.sync.aligned.m8n8.x4.trans.shared.b16 {%0,%1,%2,%3}, [%4];"
                 : "=r"(r0), "=r"(r1), "=r"(r2), "=r"(r3) : "r"(addr));
}
__device__ __forceinline__ void mma16816(float* c, const uint32_t* a, uint32_t b0, uint32_t b1) {
    asm volatile(
        "mma.sync.aligned.m16n8k16.row.col.f32.f16.f16.f32 "
        "{%0,%1,%2,%3}, {%4,%5,%6,%7}, {%8,%9}, {%0,%1,%2,%3};"
        : "+f"(c[0]), "+f"(c[1]), "+f"(c[2]), "+f"(c[3])
        : "r"(a[0]), "r"(a[1]), "r"(a[2]), "r"(a[3]), "r"(b0), "r"(b1));
}
__device__ __forceinline__ uint32_t packh(float a, float b) {
    __half2 t = __floats2half2_rn(a, b);
    return *reinterpret_cast<uint32_t*>(&t);
}

// ================= fp16 HMMA GEMM: C[M,N] = A[M,K] @ B[N,K]^T ==========
// BM=128, BN=128, BK=64, 3-stage cp.async, 8 warps (2m x 4n), 64x32/warp.
#define BM 128
#define BN 128
#define BK 64
#define LDSH  144                  // 64 fp16 = 128B + 16 pad
#define TILEH (128 * LDSH)         // 18432
#define STGH  (2 * TILEH)          // A + B
#define GEMM_SMEM (3 * STGH)       // 110592

__device__ __forceinline__ void load_stage(
    uint32_t sb, int s, const __half* A, const __half* B, int K, int k0, int tid)
{
    uint32_t st = sb + s * STGH;
#pragma unroll
    for (int t = 0; t < 4; t++) {
        int c = tid + t * 256;
        int row = c >> 3, ch = (c & 7) << 4;
        size_t go = ((size_t)row * K + k0) * 2 + ch;
        cp16(st + row * LDSH + ch,         (const char*)A + go);
        cp16(st + TILEH + row * LDSH + ch, (const char*)B + go);
    }
}

__global__ void __launch_bounds__(256, 1) gemm_h(
    const __half* __restrict__ A, const __half* __restrict__ B,
    float* __restrict__ Cf, __half* __restrict__ Ch, int N, int K)
{
    extern __shared__ char smem[];
    uint32_t sb = smem_u32(smem);
    const int tid = threadIdx.x, wid = tid >> 5, lane = tid & 31;
    const int wm = wid & 1, wn = wid >> 1;
    const int bm0 = blockIdx.y * BM;
    const int bn0 = blockIdx.x * BN;

    const __half* pA = A + (size_t)bm0 * K;
    const __half* pB = B + (size_t)bn0 * K;

    float acc[4][4][4];
#pragma unroll
    for (int i = 0; i < 4; i++)
#pragma unroll
        for (int j = 0; j < 4; j++)
#pragma unroll
            for (int r = 0; r < 4; r++) acc[i][j][r] = 0.f;

    const int NIT = K / BK;
    load_stage(sb, 0, pA, pB, K, 0, tid);
    cp_commit();
    load_stage(sb, 1, pA, pB, K, BK, tid);
    cp_commit();

    const int a_row = wm * 64 + (lane & 15);
    const int a_col = (lane >> 4) << 3;
    const int bg = lane >> 3;
    const int b_row = wn * 32 + ((bg >> 1) << 3) + (lane & 7);
    const int b_col = (bg & 1) << 3;

    int sidx = 0;
    for (int it = 0; it < NIT; ++it) {
        if (it + 2 < NIT) {
            load_stage(sb, (it + 2) % 3, pA, pB, K, (it + 2) * BK, tid);
            cp_commit();
            cp_wait2();
        } else if (it + 1 < NIT) {
            cp_wait1();
        } else {
            cp_wait0();
        }
        __syncthreads();

        uint32_t st = sb + sidx * STGH;
        sidx = (sidx + 1 == 3) ? 0 : sidx + 1;
#pragma unroll
        for (int ks = 0; ks < 4; ks++) {
            uint32_t af[4][4];
#pragma unroll
            for (int mi = 0; mi < 4; mi++) {
                uint32_t ad = st + (a_row + mi * 16) * LDSH + (a_col + ks * 16) * 2;
                ldsm4(af[mi][0], af[mi][1], af[mi][2], af[mi][3], ad);
            }
            uint32_t bf[4][2];
#pragma unroll
            for (int p = 0; p < 2; p++) {
                uint32_t bd = st + TILEH + (b_row + p * 16) * LDSH + (b_col + ks * 16) * 2;
                ldsm4(bf[2*p][0], bf[2*p][1], bf[2*p+1][0], bf[2*p+1][1], bd);
            }
#pragma unroll
            for (int mi = 0; mi < 4; mi++)
#pragma unroll
                for (int ni = 0; ni < 4; ni++)
                    mma16816(acc[mi][ni], af[mi], bf[ni][0], bf[ni][1]);
        }
        __syncthreads();
    }

    const int cr = lane >> 2, cc = (lane & 3) << 1;
#pragma unroll
    for (int mi = 0; mi < 4; mi++) {
        int r0 = bm0 + wm * 64 + mi * 16 + cr;
#pragma unroll
        for (int ni = 0; ni < 4; ni++) {
            int col = bn0 + wn * 32 + ni * 8 + cc;
            if (Ch) {
                *(__half2*)(Ch + (size_t)r0 * N + col) =
                    __floats2half2_rn(acc[mi][ni][0], acc[mi][ni][1]);
                *(__half2*)(Ch + (size_t)(r0 + 8) * N + col) =
                    __floats2half2_rn(acc[mi][ni][2], acc[mi][ni][3]);
            } else {
                *(float2*)(Cf + (size_t)r0 * N + col) =
                    make_float2(acc[mi][ni][0], acc[mi][ni][1]);
                *(float2*)(Cf + (size_t)(r0 + 8) * N + col) =
                    make_float2(acc[mi][ni][2], acc[mi][ni][3]);
            }
        }
    }
}

// ================= fp32 -> fp16 convert =================
__global__ void cvt_kernel(const float* __restrict__ src, __half* __restrict__ dst, int n4)
{
    int i = blockIdx.x * blockDim.x + threadIdx.x;
    if (i >= n4) return;
    float4 v = ((const float4*)src)[i];
    __half2 a = __floats2half2_rn(v.x, v.y);
    __half2 b = __floats2half2_rn(v.z, v.w);
    ((uint2*)dst)[i] = make_uint2(*(uint32_t*)&a, *(uint32_t*)&b);
}

// ============= transpose + convert: w[K,N] -> wT[N,K] fp16 =============
__global__ void __launch_bounds__(256) tcvt_kernel(
    const float* __restrict__ w, __half* __restrict__ t16, int K, int N)
{
    __shared__ float t[32][33];
    const int n0 = blockIdx.x * 32, k0 = blockIdx.y * 32;
    const int tx = threadIdx.x & 31, ty = threadIdx.x >> 5;
#pragma unroll
    for (int i = 0; i < 32; i += 8)
        t[ty + i][tx] = w[(size_t)(k0 + ty + i) * N + n0 + tx];
    __syncthreads();
#pragma unroll
    for (int i = 0; i < 32; i += 8)
        t16[(size_t)(n0 + ty + i) * K + k0 + tx] = __float2half(t[tx][ty + i]);
}

// ========== fused RoPE + optional scale, fp32 -> fp16 ==========
__global__ void rope_h(const float* __restrict__ t,
                       const float* __restrict__ fc, const float* __restrict__ fs,
                       __half* __restrict__ o, int nheads, int total, float scl)
{
    int idx = blockIdx.x * blockDim.x + threadIdx.x;
    if (idx >= total) return;
    int j = idx & 63;
    int s = (idx / (64 * nheads)) % SEQ;
    float c = fc[s * 64 + j], sn = fs[s * 64 + j];
    float2 v = ((const float2*)t)[idx];
    float re = (v.x * c - v.y * sn) * scl;
    float im = (v.x * sn + v.y * c) * scl;
    ((__half2*)o)[idx] = __floats2half2_rn(re, im);
}

// ================= fp16 HMMA flash attention =================
// CTA: (q-tile 128, head, batch). 8 warps x 16 q-rows. KV tiles of 64 keys.
#define AT_LDS 272                          // 128 fp16 = 256B + 16 pad
#define AT_QT  (128 * AT_LDS)               // 34816
#define AT_KVT (64 * AT_LDS)                // 17408
#define AT_STG (2 * AT_KVT)                 // K, V
#define ATTN_SMEM (AT_QT + 2 * AT_STG)      // 104448

__global__ void __launch_bounds__(256, 1) attn_h(
    const __half* __restrict__ Qh, const __half* __restrict__ Kh,
    const __half* __restrict__ Vh, __half* __restrict__ Oh)
{
    extern __shared__ char sm_[];
    uint32_t sb = smem_u32(sm_);
    const int tid = threadIdx.x, wid = tid >> 5, lane = tid & 31;
    const int qt = gridDim.x - 1 - blockIdx.x;       // heavy tiles first
    const int h = blockIdx.y, b = blockIdx.z;
    const int q0 = qt * 128, kvh = h >> 2;
    const int nkv = 2 * qt + 2;

    const char* Qg = (const char*)(Qh + ((size_t)(b * SEQ + q0) * NH + h) * HD);
    const char* Kg = (const char*)(Kh + ((size_t)(b * SEQ) * NKV + kvh) * HD);
    const char* Vg = (const char*)(Vh + ((size_t)(b * SEQ) * NKV + kvh) * HD);

    for (int c = tid; c < 128 * 16; c += 256) {
        int r = c >> 4, ch = (c & 15) << 4;
        cp16(sb + r * AT_LDS + ch, Qg + (size_t)r * 8192 + ch);
    }
    auto load_kv = [&](int kt, int s) {
        uint32_t st = sb + AT_QT + s * AT_STG;
        size_t gof = (size_t)kt * 64 * 2048;
        for (int c = tid; c < 64 * 16; c += 256) {
            int r = c >> 4, ch = (c & 15) << 4;
            size_t g = gof + (size_t)r * 2048 + ch;
            cp16(st + r * AT_LDS + ch,          Kg + g);
            cp16(st + AT_KVT + r * AT_LDS + ch, Vg + g);
        }
    };
    load_kv(0, 0);
    cp_commit();

    uint32_t qf[8][4];
    float oacc[16][4];
#pragma unroll
    for (int i = 0; i < 16; i++)
#pragma unroll
        for (int r = 0; r < 4; r++) oacc[i][r] = 0.f;
    float mrow0 = -1e30f, mrow1 = -1e30f, lrow0 = 0.f, lrow1 = 0.f;

    const int bg = lane >> 3;
    const int kb_row = ((bg >> 1) << 3) + (lane & 7);
    const int kb_col = (bg & 1) << 3;

    for (int kt = 0; kt < nkv; kt++) {
        if (kt + 1 < nkv) { load_kv(kt + 1, (kt + 1) & 1); cp_commit(); cp_wait1(); }
        else             { cp_wait0(); }
        __syncthreads();

        if (kt == 0) {
            uint32_t qa = sb + (wid * 16 + (lane & 15)) * AT_LDS + ((lane >> 4) << 3) * 2;
#pragma unroll
            for (int kc = 0; kc < 8; kc++)
                ldsm4(qf[kc][0], qf[kc][1], qf[kc][2], qf[kc][3], qa + kc * 32);
        }
        uint32_t st = sb + AT_QT + (kt & 1) * AT_STG;

        // ---- S = Q K^T ----
        float sacc[8][4];
#pragma unroll
        for (int i = 0; i < 8; i++)
#pragma unroll
            for (int r = 0; r < 4; r++) sacc[i][r] = 0.f;

#pragma unroll
        for (int kc = 0; kc < 8; kc++) {
#pragma unroll
            for (int pr = 0; pr < 4; pr++) {
                uint32_t bd = st + (pr * 16 + kb_row) * AT_LDS + (kc * 16 + kb_col) * 2;
                uint32_t k0r, k1r, k2r, k3r;
                ldsm4(k0r, k1r, k2r, k3r, bd);
                mma16816(sacc[2*pr],   qf[kc], k0r, k1r);
                mma16816(sacc[2*pr+1], qf[kc], k2r, k3r);
            }
        }

        // ---- causal mask ----
        const int k0g = kt * 64;
        const int rlo = q0 + wid * 16 + (lane >> 2);
        if (kt >= nkv - 2) {
#pragma unroll
            for (int nj = 0; nj < 8; nj++) {
                int key = k0g + nj * 8 + ((lane & 3) << 1);
                if (key     > rlo)     sacc[nj][0] = -1e30f;
                if (key + 1 > rlo)     sacc[nj][1] = -1e30f;
                if (key     > rlo + 8) sacc[nj][2] = -1e30f;
                if (key + 1 > rlo + 8) sacc[nj][3] = -1e30f;
            }
        }

        // ---- online softmax ----
        float mx0 = -1e30f, mx1 = -1e30f;
#pragma unroll
        for (int nj = 0; nj < 8; nj++) {
            mx0 = fmaxf(mx0, fmaxf(sacc[nj][0], sacc[nj][1]));
            mx1 = fmaxf(mx1, fmaxf(sacc[nj][2], sacc[nj][3]));
        }
        mx0 = fmaxf(mx0, __shfl_xor_sync(0xffffffffu, mx0, 1));
        mx0 = fmaxf(mx0, __shfl_xor_sync(0xffffffffu, mx0, 2));
        mx1 = fmaxf(mx1, __shfl_xor_sync(0xffffffffu, mx1, 1));
        mx1 = fmaxf(mx1, __shfl_xor_sync(0xffffffffu, mx1, 2));
        float mn0 = fmaxf(mrow0, mx0), mn1 = fmaxf(mrow1, mx1);
        float cr0 = __expf(mrow0 - mn0), cr1 = __expf(mrow1 - mn1);
        mrow0 = mn0; mrow1 = mn1;
        float sum0 = 0.f, sum1 = 0.f;
#pragma unroll
        for (int nj = 0; nj < 8; nj++) {
            float p0 = __expf(sacc[nj][0] - mn0); sacc[nj][0] = p0; sum0 += p0;
            float p1 = __expf(sacc[nj][1] - mn0); sacc[nj][1] = p1; sum0 += p1;
            float p2 = __expf(sacc[nj][2] - mn1); sacc[nj][2] = p2; sum1 += p2;
            float p3 = __expf(sacc[nj][3] - mn1); sacc[nj][3] = p3; sum1 += p3;
        }
        sum0 += __shfl_xor_sync(0xffffffffu, sum0, 1);
        sum0 += __shfl_xor_sync(0xffffffffu, sum0, 2);
        sum1 += __shfl_xor_sync(0xffffffffu, sum1, 1);
        sum1 += __shfl_xor_sync(0xffffffffu, sum1, 2);
        lrow0 = lrow0 * cr0 + sum0;
        lrow1 = lrow1 * cr1 + sum1;
#pragma unroll
        for (int nj = 0; nj < 16; nj++) {
            oacc[nj][0] *= cr0; oacc[nj][1] *= cr0;
            oacc[nj][2] *= cr1; oacc[nj][3] *= cr1;
        }

        // ---- O += P V ----
#pragma unroll
        for (int kc = 0; kc < 4; kc++) {
            uint32_t pa[4];
            pa[0] = packh(sacc[2*kc][0],   sacc[2*kc][1]);
            pa[1] = packh(sacc[2*kc][2],   sacc[2*kc][3]);
            pa[2] = packh(sacc[2*kc+1][0], sacc[2*kc+1][1]);
            pa[3] = packh(sacc[2*kc+1][2], sacc[2*kc+1][3]);
            uint32_t vrow = st + AT_KVT + (kc * 16 + (lane & 15)) * AT_LDS
                          + ((lane >> 4) << 3) * 2;
#pragma unroll
            for (int g = 0; g < 8; g++) {
                uint32_t v0, v1, v2, v3;
                ldsm4t(v0, v1, v2, v3, vrow + g * 32);
                mma16816(oacc[2*g],   pa, v0, v1);
                mma16816(oacc[2*g+1], pa, v2, v3);
            }
        }
        __syncthreads();
    }

    // ---- epilogue: normalize, store fp16 ----
    float inv0 = 1.f / lrow0, inv1 = 1.f / lrow1;
    const int rlo = q0 + wid * 16 + (lane >> 2);
    size_t base_lo = ((size_t)(b * SEQ + rlo) * NH + h) * HD + ((lane & 3) << 1);
    size_t base_hi = base_lo + (size_t)8 * NH * HD;
#pragma unroll
    for (int nj = 0; nj < 16; nj++) {
        *(__half2*)(Oh + base_lo + nj * 8) =
            __floats2half2_rn(oacc[nj][0] * inv0, oacc[nj][1] * inv0);
        *(__half2*)(Oh + base_hi + nj * 8) =
            __floats2half2_rn(oacc[nj][2] * inv1, oacc[nj][3] * inv1);
    }
}

// ============================ launch ======================================
extern "C" void kernel_launch(void* const* d_in, const int* in_sizes, int n_in,
                              void* d_out, int out_size)
{
    const float* x  = (const float*)d_in[0];
    const float* wq = (const float*)d_in[1];
    const float* wk = (const float*)d_in[2];
    const float* wv = (const float*)d_in[3];
    const float* wo = (const float*)d_in[4];
    const float* fc = (const float*)d_in[7];
    const float* fs = (const float*)d_in[8];
    float* out = (float*)d_out;
    (void)in_sizes; (void)n_in; (void)out_size;

    float *q, *k;
    __half *xh, *wqt, *wkt, *wvt, *wot, *att, *qh, *kh, *vh;
    cudaGetSymbolAddress((void**)&q,   g_q);
    cudaGetSymbolAddress((void**)&k,   g_k);
    cudaGetSymbolAddress((void**)&xh,  g_xh);
    cudaGetSymbolAddress((void**)&wqt, g_wqt);
    cudaGetSymbolAddress((void**)&wkt, g_wkt);
    cudaGetSymbolAddress((void**)&wvt, g_wvt);
    cudaGetSymbolAddress((void**)&wot, g_wot);
    cudaGetSymbolAddress((void**)&att, g_att);
    cudaGetSymbolAddress((void**)&qh,  g_qh);
    cudaGetSymbolAddress((void**)&kh,  g_kh);
    cudaGetSymbolAddress((void**)&vh,  g_vh);

    cudaFuncSetAttribute(gemm_h, cudaFuncAttributeMaxDynamicSharedMemorySize, GEMM_SMEM);
    cudaFuncSetAttribute(attn_h, cudaFuncAttributeMaxDynamicSharedMemorySize, ATTN_SMEM);

    // ---- prep: convert x, transpose+convert weights ----
    const int n4x = TOKENS * DIMV / 4;
    cvt_kernel<<<n4x / 256, 256>>>(x, xh, n4x);
    tcvt_kernel<<<dim3(DIMV / 32,     DIMV / 32), 256>>>(wq, wqt, DIMV, DIMV);
    tcvt_kernel<<<dim3(NKV * HD / 32, DIMV / 32), 256>>>(wk, wkt, DIMV, NKV * HD);
    tcvt_kernel<<<dim3(NKV * HD / 32, DIMV / 32), 256>>>(wv, wvt, DIMV, NKV * HD);
    tcvt_kernel<<<dim3(DIMV / 32,     DIMV / 32), 256>>>(wo, wot, DIMV, DIMV);

    // ---- projections (fp16 HMMA); V writes fp16 directly ----
    gemm_h<<<dim3((NH*HD)/BN,  TOKENS/BM), 256, GEMM_SMEM>>>(xh, wqt, q, nullptr, NH*HD,  DIMV);
    gemm_h<<<dim3((NKV*HD)/BN, TOKENS/BM), 256, GEMM_SMEM>>>(xh, wkt, k, nullptr, NKV*HD, DIMV);
    gemm_h<<<dim3((NKV*HD)/BN, TOKENS/BM), 256, GEMM_SMEM>>>(xh, wvt, nullptr, vh, NKV*HD, DIMV);

    // ---- fused RoPE (+softmax scale into Q) ----
    {
        const float scale = 0.08838834764831845f;  // 1/sqrt(128)
        int tq = TOKENS * NH * 64;
        int tk = TOKENS * NKV * 64;
        rope_h<<<tq / 256, 256>>>(q, fc, fs, qh, NH,  tq, scale);
        rope_h<<<tk / 256, 256>>>(k, fc, fs, kh, NKV, tk, 1.0f);
    }

    // ---- flash attention (fp16 HMMA) ----
    attn_h<<<dim3(SEQ / 128, NH, BATCH_), 256, ATTN_SMEM>>>(qh, kh, vh, att);

    // ---- output projection ----
    gemm_h<<<dim3(DIMV/BN, TOKENS/BM), 256, GEMM_SMEM>>>(att, wot, out, nullptr, DIMV, DIMV);
}

// round 6
// speedup vs baseline: 7.2544x; 1.0012x over previous
#include <cuda_runtime.h>
#include <cuda_fp16.h>
#include <math.h>
#include <stdint.h>

#define BATCH_ 2
#define SEQ    2048
#define DIMV   4096
#define NH     32
#define NKV    8
#define HD     128
#define TOKENS (BATCH_*SEQ)   // 4096
#define NQKV   (DIMV + 2*NKV*HD)   // 6144

// ---------------- scratch (no cudaMalloc allowed) ----------------
__device__ __align__(1024) float  g_qkv  [(size_t)TOKENS * NQKV];     // fused QKV out (fp32)
__device__ __align__(1024) __half g_xh   [(size_t)TOKENS * DIMV];
__device__ __align__(1024) __half g_wqkvt[(size_t)NQKV * DIMV];       // [6144][4096]
__device__ __align__(1024) __half g_wot  [(size_t)DIMV * DIMV];
__device__ __align__(1024) __half g_att  [(size_t)TOKENS * DIMV];
__device__ __align__(1024) __half g_qh   [(size_t)TOKENS * NH  * HD];
__device__ __align__(1024) __half g_kh   [(size_t)TOKENS * NKV * HD];
__device__ __align__(1024) __half g_vh   [(size_t)TOKENS * NKV * HD];

// ================= helpers =================
__device__ __forceinline__ uint32_t smem_u32(const void* p) {
    return (uint32_t)__cvta_generic_to_shared(p);
}
__device__ __forceinline__ void cp16(uint32_t dst, const void* src) {
    asm volatile("cp.async.cg.shared.global [%0], [%1], 16;" :: "r"(dst), "l"(src));
}
__device__ __forceinline__ void cp_commit() {
    asm volatile("cp.async.commit_group;" ::: "memory");
}
__device__ __forceinline__ void cp_wait2() {
    asm volatile("cp.async.wait_group 2;" ::: "memory");
}
__device__ __forceinline__ void cp_wait1() {
    asm volatile("cp.async.wait_group 1;" ::: "memory");
}
__device__ __forceinline__ void cp_wait0() {
    asm volatile("cp.async.wait_group 0;" ::: "memory");
}
__device__ __forceinline__ void ldsm4(uint32_t& r0, uint32_t& r1, uint32_t& r2, uint32_t& r3,
                                      uint32_t addr) {
    asm volatile("ldmatrix.sync.aligned.m8n8.x4.shared.b16 {%0,%1,%2,%3}, [%4];"
                 : "=r"(r0), "=r"(r1), "=r"(r2), "=r"(r3) : "r"(addr));
}
__device__ __forceinline__ void ldsm4t(uint32_t& r0, uint32_t& r1, uint32_t& r2, uint32_t& r3,
                                       uint32_t addr) {
    asm volatile("ldmatrix.sync.aligned.m8n8.x4.trans.shared.b16 {%0,%1,%2,%3}, [%4];"
                 : "=r"(r0), "=r"(r1), "=r"(r2), "=r"(r3) : "r"(addr));
}
__device__ __forceinline__ void mma16816(float* c, const uint32_t* a, uint32_t b0, uint32_t b1) {
    asm volatile(
        "mma.sync.aligned.m16n8k16.row.col.f32.f16.f16.f32 "
        "{%0,%1,%2,%3}, {%4,%5,%6,%7}, {%8,%9}, {%0,%1,%2,%3};"
        : "+f"(c[0]), "+f"(c[1]), "+f"(c[2]), "+f"(c[3])
        : "r"(a[0]), "r"(a[1]), "r"(a[2]), "r"(a[3]), "r"(b0), "r"(b1));
}
__device__ __forceinline__ uint32_t packh(float a, float b) {
    __half2 t = __floats2half2_rn(a, b);
    return *reinterpret_cast<uint32_t*>(&t);
}

// ================= fp16 HMMA GEMM: C[M,N] = A[M,K] @ B[N,K]^T ==========
// BM=128, BN=128, BK=64, 3-stage cp.async, 8 warps (2m x 4n), 64x32/warp.
// (numeric path identical to R5)
#define BM 128
#define BN 128
#define BK 64
#define LDSH  144
#define TILEH (128 * LDSH)
#define STGH  (2 * TILEH)
#define GEMM_SMEM (3 * STGH)

__device__ __forceinline__ void load_stage(
    uint32_t sb, int s, const __half* A, const __half* B, int K, int k0, int tid)
{
    uint32_t st = sb + s * STGH;
#pragma unroll
    for (int t = 0; t < 4; t++) {
        int c = tid + t * 256;
        int row = c >> 3, ch = (c & 7) << 4;
        size_t go = ((size_t)row * K + k0) * 2 + ch;
        cp16(st + row * LDSH + ch,         (const char*)A + go);
        cp16(st + TILEH + row * LDSH + ch, (const char*)B + go);
    }
}

__global__ void __launch_bounds__(256, 1) gemm_h(
    const __half* __restrict__ A, const __half* __restrict__ B,
    float* __restrict__ Cf, __half* __restrict__ Ch, int N, int K)
{
    extern __shared__ char smem[];
    uint32_t sb = smem_u32(smem);
    const int tid = threadIdx.x, wid = tid >> 5, lane = tid & 31;
    const int wm = wid & 1, wn = wid >> 1;
    const int bm0 = blockIdx.y * BM;
    const int bn0 = blockIdx.x * BN;

    const __half* pA = A + (size_t)bm0 * K;
    const __half* pB = B + (size_t)bn0 * K;

    float acc[4][4][4];
#pragma unroll
    for (int i = 0; i < 4; i++)
#pragma unroll
        for (int j = 0; j < 4; j++)
#pragma unroll
            for (int r = 0; r < 4; r++) acc[i][j][r] = 0.f;

    const int NIT = K / BK;
    load_stage(sb, 0, pA, pB, K, 0, tid);
    cp_commit();
    load_stage(sb, 1, pA, pB, K, BK, tid);
    cp_commit();

    const int a_row = wm * 64 + (lane & 15);
    const int a_col = (lane >> 4) << 3;
    const int bg = lane >> 3;
    const int b_row = wn * 32 + ((bg >> 1) << 3) + (lane & 7);
    const int b_col = (bg & 1) << 3;

    int sidx = 0;
    for (int it = 0; it < NIT; ++it) {
        if (it + 2 < NIT) {
            load_stage(sb, (it + 2) % 3, pA, pB, K, (it + 2) * BK, tid);
            cp_commit();
            cp_wait2();
        } else if (it + 1 < NIT) {
            cp_wait1();
        } else {
            cp_wait0();
        }
        __syncthreads();

        uint32_t st = sb + sidx * STGH;
        sidx = (sidx + 1 == 3) ? 0 : sidx + 1;
#pragma unroll
        for (int ks = 0; ks < 4; ks++) {
            uint32_t af[4][4];
#pragma unroll
            for (int mi = 0; mi < 4; mi++) {
                uint32_t ad = st + (a_row + mi * 16) * LDSH + (a_col + ks * 16) * 2;
                ldsm4(af[mi][0], af[mi][1], af[mi][2], af[mi][3], ad);
            }
            uint32_t bf[4][2];
#pragma unroll
            for (int p = 0; p < 2; p++) {
                uint32_t bd = st + TILEH + (b_row + p * 16) * LDSH + (b_col + ks * 16) * 2;
                ldsm4(bf[2*p][0], bf[2*p][1], bf[2*p+1][0], bf[2*p+1][1], bd);
            }
#pragma unroll
            for (int mi = 0; mi < 4; mi++)
#pragma unroll
                for (int ni = 0; ni < 4; ni++)
                    mma16816(acc[mi][ni], af[mi], bf[ni][0], bf[ni][1]);
        }
        __syncthreads();
    }

    const int cr = lane >> 2, cc = (lane & 3) << 1;
#pragma unroll
    for (int mi = 0; mi < 4; mi++) {
        int r0 = bm0 + wm * 64 + mi * 16 + cr;
#pragma unroll
        for (int ni = 0; ni < 4; ni++) {
            int col = bn0 + wn * 32 + ni * 8 + cc;
            if (Ch) {
                *(__half2*)(Ch + (size_t)r0 * N + col) =
                    __floats2half2_rn(acc[mi][ni][0], acc[mi][ni][1]);
                *(__half2*)(Ch + (size_t)(r0 + 8) * N + col) =
                    __floats2half2_rn(acc[mi][ni][2], acc[mi][ni][3]);
            } else {
                *(float2*)(Cf + (size_t)r0 * N + col) =
                    make_float2(acc[mi][ni][0], acc[mi][ni][1]);
                *(float2*)(Cf + (size_t)(r0 + 8) * N + col) =
                    make_float2(acc[mi][ni][2], acc[mi][ni][3]);
            }
        }
    }
}

// ================= fp32 -> fp16 convert (packed) =================
__global__ void cvt_kernel(const float* __restrict__ src, __half* __restrict__ dst, int n4)
{
    int i = blockIdx.x * blockDim.x + threadIdx.x;
    if (i >= n4) return;
    float4 v = ((const float4*)src)[i];
    __half2 a = __floats2half2_rn(v.x, v.y);
    __half2 b = __floats2half2_rn(v.z, v.w);
    ((uint2*)dst)[i] = make_uint2(*(uint32_t*)&a, *(uint32_t*)&b);
}

// ======== strided fp32 -> fp16 convert: V slice of fused qkv =========
__global__ void cvt_v_kernel(const float* __restrict__ qkv, __half* __restrict__ dst, int total4)
{
    int i = blockIdx.x * blockDim.x + threadIdx.x;
    if (i >= total4) return;
    int tok = i >> 8, j = i & 255;                      // 1024 halfs = 256 float4 per token
    float4 v = ((const float4*)qkv)[(size_t)tok * (NQKV/4) + (DIMV + NKV*HD)/4 + j];
    __half2 a = __floats2half2_rn(v.x, v.y);
    __half2 b = __floats2half2_rn(v.z, v.w);
    ((uint2*)dst)[(size_t)tok * 256 + j] = make_uint2(*(uint32_t*)&a, *(uint32_t*)&b);
}

// ===== transpose + convert: w[K,N] -> wT[N,K] fp16, 64x64 tiles ======
__global__ void __launch_bounds__(256) tcvt_kernel(
    const float* __restrict__ w, __half* __restrict__ t16, int K, int N)
{
    __shared__ float t[64][65];
    const int n0 = blockIdx.x * 64, k0 = blockIdx.y * 64;
    const int tid = threadIdx.x;

    // load 64x64 floats: thread -> row tid/16, 4 cols at (tid%16)*4; 4 row-iters
    {
        int r = tid >> 4, c4 = (tid & 15) << 2;
#pragma unroll
        for (int i = 0; i < 4; i++) {
            float4 v = *(const float4*)(w + (size_t)(k0 + r + i * 16) * N + n0 + c4);
            t[r + i * 16][c4 + 0] = v.x;
            t[r + i * 16][c4 + 1] = v.y;
            t[r + i * 16][c4 + 2] = v.z;
            t[r + i * 16][c4 + 3] = v.w;
        }
    }
    __syncthreads();

    // store: thread -> output row n_local = tid/4, 16 halfs at k = (tid%4)*16
    {
        int nl = tid >> 2, kc = (tid & 3) << 4;
        __half hv[16];
#pragma unroll
        for (int i = 0; i < 16; i++)
            hv[i] = __float2half(t[kc + i][nl]);
        *(uint4*)(t16 + (size_t)(n0 + nl) * K + k0 + kc)     = *(uint4*)&hv[0];
        *(uint4*)(t16 + (size_t)(n0 + nl) * K + k0 + kc + 8) = *(uint4*)&hv[8];
    }
}

// ========== fused RoPE + optional scale, strided fp32 src -> fp16 ==========
// src is [tok][tok_stride_f2] float2; this head-group starts at tok_off_f2.
__global__ void rope_h(const float* __restrict__ t,
                       const float* __restrict__ fc, const float* __restrict__ fs,
                       __half* __restrict__ o, int nheads, int total, float scl,
                       int tok_stride_f2, int tok_off_f2)
{
    int idx = blockIdx.x * blockDim.x + threadIdx.x;
    if (idx >= total) return;
    int pairs = 64 * nheads;
    int tok = idx / pairs;
    int within = idx - tok * pairs;
    int j = idx & 63;
    int s = tok % SEQ;
    float c = fc[s * 64 + j], sn = fs[s * 64 + j];
    float2 v = ((const float2*)t)[(size_t)tok * tok_stride_f2 + tok_off_f2 + within];
    float re = (v.x * c - v.y * sn) * scl;
    float im = (v.x * sn + v.y * c) * scl;
    ((__half2*)o)[idx] = __floats2half2_rn(re, im);
}

// ================= fp16 HMMA flash attention (unchanged from R5) ==========
#define AT_LDS 272
#define AT_QT  (128 * AT_LDS)
#define AT_KVT (64 * AT_LDS)
#define AT_STG (2 * AT_KVT)
#define ATTN_SMEM (AT_QT + 2 * AT_STG)

__global__ void __launch_bounds__(256, 1) attn_h(
    const __half* __restrict__ Qh, const __half* __restrict__ Kh,
    const __half* __restrict__ Vh, __half* __restrict__ Oh)
{
    extern __shared__ char sm_[];
    uint32_t sb = smem_u32(sm_);
    const int tid = threadIdx.x, wid = tid >> 5, lane = tid & 31;
    const int qt = gridDim.x - 1 - blockIdx.x;
    const int h = blockIdx.y, b = blockIdx.z;
    const int q0 = qt * 128, kvh = h >> 2;
    const int nkv = 2 * qt + 2;

    const char* Qg = (const char*)(Qh + ((size_t)(b * SEQ + q0) * NH + h) * HD);
    const char* Kg = (const char*)(Kh + ((size_t)(b * SEQ) * NKV + kvh) * HD);
    const char* Vg = (const char*)(Vh + ((size_t)(b * SEQ) * NKV + kvh) * HD);

    for (int c = tid; c < 128 * 16; c += 256) {
        int r = c >> 4, ch = (c & 15) << 4;
        cp16(sb + r * AT_LDS + ch, Qg + (size_t)r * 8192 + ch);
    }
    auto load_kv = [&](int kt, int s) {
        uint32_t st = sb + AT_QT + s * AT_STG;
        size_t gof = (size_t)kt * 64 * 2048;
        for (int c = tid; c < 64 * 16; c += 256) {
            int r = c >> 4, ch = (c & 15) << 4;
            size_t g = gof + (size_t)r * 2048 + ch;
            cp16(st + r * AT_LDS + ch,          Kg + g);
            cp16(st + AT_KVT + r * AT_LDS + ch, Vg + g);
        }
    };
    load_kv(0, 0);
    cp_commit();

    uint32_t qf[8][4];
    float oacc[16][4];
#pragma unroll
    for (int i = 0; i < 16; i++)
#pragma unroll
        for (int r = 0; r < 4; r++) oacc[i][r] = 0.f;
    float mrow0 = -1e30f, mrow1 = -1e30f, lrow0 = 0.f, lrow1 = 0.f;

    const int bg = lane >> 3;
    const int kb_row = ((bg >> 1) << 3) + (lane & 7);
    const int kb_col = (bg & 1) << 3;

    for (int kt = 0; kt < nkv; kt++) {
        if (kt + 1 < nkv) { load_kv(kt + 1, (kt + 1) & 1); cp_commit(); cp_wait1(); }
        else             { cp_wait0(); }
        __syncthreads();

        if (kt == 0) {
            uint32_t qa = sb + (wid * 16 + (lane & 15)) * AT_LDS + ((lane >> 4) << 3) * 2;
#pragma unroll
            for (int kc = 0; kc < 8; kc++)
                ldsm4(qf[kc][0], qf[kc][1], qf[kc][2], qf[kc][3], qa + kc * 32);
        }
        uint32_t st = sb + AT_QT + (kt & 1) * AT_STG;

        float sacc[8][4];
#pragma unroll
        for (int i = 0; i < 8; i++)
#pragma unroll
            for (int r = 0; r < 4; r++) sacc[i][r] = 0.f;

#pragma unroll
        for (int kc = 0; kc < 8; kc++) {
#pragma unroll
            for (int pr = 0; pr < 4; pr++) {
                uint32_t bd = st + (pr * 16 + kb_row) * AT_LDS + (kc * 16 + kb_col) * 2;
                uint32_t k0r, k1r, k2r, k3r;
                ldsm4(k0r, k1r, k2r, k3r, bd);
                mma16816(sacc[2*pr],   qf[kc], k0r, k1r);
                mma16816(sacc[2*pr+1], qf[kc], k2r, k3r);
            }
        }

        const int k0g = kt * 64;
        const int rlo = q0 + wid * 16 + (lane >> 2);
        if (kt >= nkv - 2) {
#pragma unroll
            for (int nj = 0; nj < 8; nj++) {
                int key = k0g + nj * 8 + ((lane & 3) << 1);
                if (key     > rlo)     sacc[nj][0] = -1e30f;
                if (key + 1 > rlo)     sacc[nj][1] = -1e30f;
                if (key     > rlo + 8) sacc[nj][2] = -1e30f;
                if (key + 1 > rlo + 8) sacc[nj][3] = -1e30f;
            }
        }

        float mx0 = -1e30f, mx1 = -1e30f;
#pragma unroll
        for (int nj = 0; nj < 8; nj++) {
            mx0 = fmaxf(mx0, fmaxf(sacc[nj][0], sacc[nj][1]));
            mx1 = fmaxf(mx1, fmaxf(sacc[nj][2], sacc[nj][3]));
        }
        mx0 = fmaxf(mx0, __shfl_xor_sync(0xffffffffu, mx0, 1));
        mx0 = fmaxf(mx0, __shfl_xor_sync(0xffffffffu, mx0, 2));
        mx1 = fmaxf(mx1, __shfl_xor_sync(0xffffffffu, mx1, 1));
        mx1 = fmaxf(mx1, __shfl_xor_sync(0xffffffffu, mx1, 2));
        float mn0 = fmaxf(mrow0, mx0), mn1 = fmaxf(mrow1, mx1);
        float cr0 = __expf(mrow0 - mn0), cr1 = __expf(mrow1 - mn1);
        mrow0 = mn0; mrow1 = mn1;
        float sum0 = 0.f, sum1 = 0.f;
#pragma unroll
        for (int nj = 0; nj < 8; nj++) {
            float p0 = __expf(sacc[nj][0] - mn0); sacc[nj][0] = p0; sum0 += p0;
            float p1 = __expf(sacc[nj][1] - mn0); sacc[nj][1] = p1; sum0 += p1;
            float p2 = __expf(sacc[nj][2] - mn1); sacc[nj][2] = p2; sum1 += p2;
            float p3 = __expf(sacc[nj][3] - mn1); sacc[nj][3] = p3; sum1 += p3;
        }
        sum0 += __shfl_xor_sync(0xffffffffu, sum0, 1);
        sum0 += __shfl_xor_sync(0xffffffffu, sum0, 2);
        sum1 += __shfl_xor_sync(0xffffffffu, sum1, 1);
        sum1 += __shfl_xor_sync(0xffffffffu, sum1, 2);
        lrow0 = lrow0 * cr0 + sum0;
        lrow1 = lrow1 * cr1 + sum1;
#pragma unroll
        for (int nj = 0; nj < 16; nj++) {
            oacc[nj][0] *= cr0; oacc[nj][1] *= cr0;
            oacc[nj][2] *= cr1; oacc[nj][3] *= cr1;
        }

#pragma unroll
        for (int kc = 0; kc < 4; kc++) {
            uint32_t pa[4];
            pa[0] = packh(sacc[2*kc][0],   sacc[2*kc][1]);
            pa[1] = packh(sacc[2*kc][2],   sacc[2*kc][3]);
            pa[2] = packh(sacc[2*kc+1][0], sacc[2*kc+1][1]);
            pa[3] = packh(sacc[2*kc+1][2], sacc[2*kc+1][3]);
            uint32_t vrow = st + AT_KVT + (kc * 16 + (lane & 15)) * AT_LDS
                          + ((lane >> 4) << 3) * 2;
#pragma unroll
            for (int g = 0; g < 8; g++) {
                uint32_t v0, v1, v2, v3;
                ldsm4t(v0, v1, v2, v3, vrow + g * 32);
                mma16816(oacc[2*g],   pa, v0, v1);
                mma16816(oacc[2*g+1], pa, v2, v3);
            }
        }
        __syncthreads();
    }

    float inv0 = 1.f / lrow0, inv1 = 1.f / lrow1;
    const int rlo = q0 + wid * 16 + (lane >> 2);
    size_t base_lo = ((size_t)(b * SEQ + rlo) * NH + h) * HD + ((lane & 3) << 1);
    size_t base_hi = base_lo + (size_t)8 * NH * HD;
#pragma unroll
    for (int nj = 0; nj < 16; nj++) {
        *(__half2*)(Oh + base_lo + nj * 8) =
            __floats2half2_rn(oacc[nj][0] * inv0, oacc[nj][1] * inv0);
        *(__half2*)(Oh + base_hi + nj * 8) =
            __floats2half2_rn(oacc[nj][2] * inv1, oacc[nj][3] * inv1);
    }
}

// ============================ launch ======================================
extern "C" void kernel_launch(void* const* d_in, const int* in_sizes, int n_in,
                              void* d_out, int out_size)
{
    const float* x  = (const float*)d_in[0];
    const float* wq = (const float*)d_in[1];
    const float* wk = (const float*)d_in[2];
    const float* wv = (const float*)d_in[3];
    const float* wo = (const float*)d_in[4];
    const float* fc = (const float*)d_in[7];
    const float* fs = (const float*)d_in[8];
    float* out = (float*)d_out;
    (void)in_sizes; (void)n_in; (void)out_size;

    float* qkv;
    __half *xh, *wqkvt, *wot, *att, *qh, *kh, *vh;
    cudaGetSymbolAddress((void**)&qkv,   g_qkv);
    cudaGetSymbolAddress((void**)&xh,    g_xh);
    cudaGetSymbolAddress((void**)&wqkvt, g_wqkvt);
    cudaGetSymbolAddress((void**)&wot,   g_wot);
    cudaGetSymbolAddress((void**)&att,   g_att);
    cudaGetSymbolAddress((void**)&qh,    g_qh);
    cudaGetSymbolAddress((void**)&kh,    g_kh);
    cudaGetSymbolAddress((void**)&vh,    g_vh);

    cudaFuncSetAttribute(gemm_h, cudaFuncAttributeMaxDynamicSharedMemorySize, GEMM_SMEM);
    cudaFuncSetAttribute(attn_h, cudaFuncAttributeMaxDynamicSharedMemorySize, ATTN_SMEM);

    // ---- prep: convert x; transpose+convert weights into fused wqkvT + woT ----
    const int n4x = TOKENS * DIMV / 4;
    cvt_kernel<<<n4x / 256, 256>>>(x, xh, n4x);
    tcvt_kernel<<<dim3(DIMV / 64,     DIMV / 64), 256>>>(wq, wqkvt,                          DIMV, DIMV);
    tcvt_kernel<<<dim3(NKV * HD / 64, DIMV / 64), 256>>>(wk, wqkvt + (size_t)DIMV * DIMV,    DIMV, NKV * HD);
    tcvt_kernel<<<dim3(NKV * HD / 64, DIMV / 64), 256>>>(wv, wqkvt + (size_t)(DIMV + NKV*HD) * DIMV, DIMV, NKV * HD);
    tcvt_kernel<<<dim3(DIMV / 64,     DIMV / 64), 256>>>(wo, wot,                            DIMV, DIMV);

    // ---- fused QKV projection (fp16 HMMA), one launch, N=6144 ----
    gemm_h<<<dim3(NQKV / BN, TOKENS / BM), 256, GEMM_SMEM>>>(xh, wqkvt, qkv, nullptr, NQKV, DIMV);

    // ---- fused RoPE (+softmax scale into Q); strided reads from qkv ----
    {
        const float scale = 0.08838834764831845f;  // 1/sqrt(128)
        int tq = TOKENS * NH * 64;
        int tk = TOKENS * NKV * 64;
        rope_h<<<tq / 256, 256>>>(qkv, fc, fs, qh, NH,  tq, scale, NQKV / 2, 0);
        rope_h<<<tk / 256, 256>>>(qkv, fc, fs, kh, NKV, tk, 1.0f,  NQKV / 2, DIMV / 2);
        cvt_v_kernel<<<(TOKENS * 256) / 256, 256>>>(qkv, vh, TOKENS * 256);
    }

    // ---- flash attention (fp16 HMMA) ----
    attn_h<<<dim3(SEQ / 128, NH, BATCH_), 256, ATTN_SMEM>>>(qh, kh, vh, att);

    // ---- output projection ----
    gemm_h<<<dim3(DIMV / BN, TOKENS / BM), 256, GEMM_SMEM>>>(att, wot, out, nullptr, DIMV, DIMV);
}

// round 7
// speedup vs baseline: 8.2809x; 1.1415x over previous
#include <cuda_runtime.h>
#include <cuda_fp16.h>
#include <math.h>
#include <stdint.h>

#define BATCH_ 2
#define SEQ    2048
#define DIMV   4096
#define NH     32
#define NKV    8
#define HD     128
#define TOKENS (BATCH_*SEQ)   // 4096
#define NQKV   (DIMV + 2*NKV*HD)   // 6144

// ---------------- scratch (no cudaMalloc allowed) ----------------
__device__ __align__(1024) float  g_qkv  [(size_t)TOKENS * NQKV];
__device__ __align__(1024) __half g_xh   [(size_t)TOKENS * DIMV];
__device__ __align__(1024) __half g_wqkvt[(size_t)NQKV * DIMV];
__device__ __align__(1024) __half g_wot  [(size_t)DIMV * DIMV];
__device__ __align__(1024) __half g_att  [(size_t)TOKENS * DIMV];
__device__ __align__(1024) __half g_qh   [(size_t)TOKENS * NH  * HD];
__device__ __align__(1024) __half g_kh   [(size_t)TOKENS * NKV * HD];
__device__ __align__(1024) __half g_vh   [(size_t)TOKENS * NKV * HD];

// ================= helpers =================
__device__ __forceinline__ uint32_t smem_u32(const void* p) {
    return (uint32_t)__cvta_generic_to_shared(p);
}
__device__ __forceinline__ void cp16(uint32_t dst, const void* src) {
    asm volatile("cp.async.cg.shared.global [%0], [%1], 16;" :: "r"(dst), "l"(src));
}
__device__ __forceinline__ void cp_commit() {
    asm volatile("cp.async.commit_group;" ::: "memory");
}
__device__ __forceinline__ void cp_wait1() {
    asm volatile("cp.async.wait_group 1;" ::: "memory");
}
__device__ __forceinline__ void cp_wait0() {
    asm volatile("cp.async.wait_group 0;" ::: "memory");
}
__device__ __forceinline__ void ldsm4(uint32_t& r0, uint32_t& r1, uint32_t& r2, uint32_t& r3,
                                      uint32_t addr) {
    asm volatile("ldmatrix.sync.aligned.m8n8.x4.shared.b16 {%0,%1,%2,%3}, [%4];"
                 : "=r"(r0), "=r"(r1), "=r"(r2), "=r"(r3) : "r"(addr));
}
__device__ __forceinline__ void ldsm4t(uint32_t& r0, uint32_t& r1, uint32_t& r2, uint32_t& r3,
                                       uint32_t addr) {
    asm volatile("ldmatrix.sync.aligned.m8n8.x4.trans.shared.b16 {%0,%1,%2,%3}, [%4];"
                 : "=r"(r0), "=r"(r1), "=r"(r2), "=r"(r3) : "r"(addr));
}
__device__ __forceinline__ void mma16816(float* c, const uint32_t* a, uint32_t b0, uint32_t b1) {
    asm volatile(
        "mma.sync.aligned.m16n8k16.row.col.f32.f16.f16.f32 "
        "{%0,%1,%2,%3}, {%4,%5,%6,%7}, {%8,%9}, {%0,%1,%2,%3};"
        : "+f"(c[0]), "+f"(c[1]), "+f"(c[2]), "+f"(c[3])
        : "r"(a[0]), "r"(a[1]), "r"(a[2]), "r"(a[3]), "r"(b0), "r"(b1));
}
__device__ __forceinline__ uint32_t packh(float a, float b) {
    __half2 t = __floats2half2_rn(a, b);
    return *reinterpret_cast<uint32_t*>(&t);
}

// ================= fp16 HMMA GEMM: C[M,N] = A[M,K] @ B[N,K]^T ==========
// BM=128, BN=128, BK=64, 2-stage cp.async, 8 warps, 2 CTAs/SM.
// Numeric path (MMA order per output) identical to R5/R6.
#define BM 128
#define BN 128
#define BK 64
#define LDSH  144
#define TILEH (128 * LDSH)
#define STGH  (2 * TILEH)
#define GEMM_SMEM (2 * STGH)       // 73728 -> 2 CTAs/SM

__device__ __forceinline__ void load_stage(
    uint32_t sb, int s, const __half* A, const __half* B, int K, int k0, int tid)
{
    uint32_t st = sb + s * STGH;
#pragma unroll
    for (int t = 0; t < 4; t++) {
        int c = tid + t * 256;
        int row = c >> 3, ch = (c & 7) << 4;
        size_t go = ((size_t)row * K + k0) * 2 + ch;
        cp16(st + row * LDSH + ch,         (const char*)A + go);
        cp16(st + TILEH + row * LDSH + ch, (const char*)B + go);
    }
}

__global__ void __launch_bounds__(256, 2) gemm_h(
    const __half* __restrict__ A, const __half* __restrict__ B,
    float* __restrict__ Cf, __half* __restrict__ Ch, int N, int K)
{
    extern __shared__ char smem[];
    uint32_t sb = smem_u32(smem);
    const int tid = threadIdx.x, wid = tid >> 5, lane = tid & 31;
    const int wm = wid & 1, wn = wid >> 1;
    const int bm0 = blockIdx.y * BM;
    const int bn0 = blockIdx.x * BN;

    const __half* pA = A + (size_t)bm0 * K;
    const __half* pB = B + (size_t)bn0 * K;

    float acc[4][4][4];
#pragma unroll
    for (int i = 0; i < 4; i++)
#pragma unroll
        for (int j = 0; j < 4; j++)
#pragma unroll
            for (int r = 0; r < 4; r++) acc[i][j][r] = 0.f;

    const int NIT = K / BK;
    load_stage(sb, 0, pA, pB, K, 0, tid);
    cp_commit();

    const int a_row = wm * 64 + (lane & 15);
    const int a_col = (lane >> 4) << 3;
    const int bg = lane >> 3;
    const int b_row = wn * 32 + ((bg >> 1) << 3) + (lane & 7);
    const int b_col = (bg & 1) << 3;

    for (int it = 0; it < NIT; ++it) {
        if (it + 1 < NIT) {
            load_stage(sb, (it + 1) & 1, pA, pB, K, (it + 1) * BK, tid);
            cp_commit();
            cp_wait1();
        } else {
            cp_wait0();
        }
        __syncthreads();

        uint32_t st = sb + (it & 1) * STGH;
#pragma unroll
        for (int ks = 0; ks < 4; ks++) {
            uint32_t af[4][4];
#pragma unroll
            for (int mi = 0; mi < 4; mi++) {
                uint32_t ad = st + (a_row + mi * 16) * LDSH + (a_col + ks * 16) * 2;
                ldsm4(af[mi][0], af[mi][1], af[mi][2], af[mi][3], ad);
            }
            uint32_t bf[4][2];
#pragma unroll
            for (int p = 0; p < 2; p++) {
                uint32_t bd = st + TILEH + (b_row + p * 16) * LDSH + (b_col + ks * 16) * 2;
                ldsm4(bf[2*p][0], bf[2*p][1], bf[2*p+1][0], bf[2*p+1][1], bd);
            }
#pragma unroll
            for (int mi = 0; mi < 4; mi++)
#pragma unroll
                for (int ni = 0; ni < 4; ni++)
                    mma16816(acc[mi][ni], af[mi], bf[ni][0], bf[ni][1]);
        }
        __syncthreads();
    }

    const int cr = lane >> 2, cc = (lane & 3) << 1;
#pragma unroll
    for (int mi = 0; mi < 4; mi++) {
        int r0 = bm0 + wm * 64 + mi * 16 + cr;
#pragma unroll
        for (int ni = 0; ni < 4; ni++) {
            int col = bn0 + wn * 32 + ni * 8 + cc;
            if (Ch) {
                *(__half2*)(Ch + (size_t)r0 * N + col) =
                    __floats2half2_rn(acc[mi][ni][0], acc[mi][ni][1]);
                *(__half2*)(Ch + (size_t)(r0 + 8) * N + col) =
                    __floats2half2_rn(acc[mi][ni][2], acc[mi][ni][3]);
            } else {
                *(float2*)(Cf + (size_t)r0 * N + col) =
                    make_float2(acc[mi][ni][0], acc[mi][ni][1]);
                *(float2*)(Cf + (size_t)(r0 + 8) * N + col) =
                    make_float2(acc[mi][ni][2], acc[mi][ni][3]);
            }
        }
    }
}

// ================= fp32 -> fp16 convert (packed) =================
__global__ void cvt_kernel(const float* __restrict__ src, __half* __restrict__ dst, int n4)
{
    int i = blockIdx.x * blockDim.x + threadIdx.x;
    if (i >= n4) return;
    float4 v = ((const float4*)src)[i];
    __half2 a = __floats2half2_rn(v.x, v.y);
    __half2 b = __floats2half2_rn(v.z, v.w);
    ((uint2*)dst)[i] = make_uint2(*(uint32_t*)&a, *(uint32_t*)&b);
}

// ======== strided fp32 -> fp16 convert: V slice of fused qkv =========
__global__ void cvt_v_kernel(const float* __restrict__ qkv, __half* __restrict__ dst, int total4)
{
    int i = blockIdx.x * blockDim.x + threadIdx.x;
    if (i >= total4) return;
    int tok = i >> 8, j = i & 255;
    float4 v = ((const float4*)qkv)[(size_t)tok * (NQKV/4) + (DIMV + NKV*HD)/4 + j];
    __half2 a = __floats2half2_rn(v.x, v.y);
    __half2 b = __floats2half2_rn(v.z, v.w);
    ((uint2*)dst)[(size_t)tok * 256 + j] = make_uint2(*(uint32_t*)&a, *(uint32_t*)&b);
}

// ===== transpose + convert: w[K,N] -> wT[N,K] fp16, 64x64 tiles ======
__global__ void __launch_bounds__(256) tcvt_kernel(
    const float* __restrict__ w, __half* __restrict__ t16, int K, int N)
{
    __shared__ float t[64][65];
    const int n0 = blockIdx.x * 64, k0 = blockIdx.y * 64;
    const int tid = threadIdx.x;
    {
        int r = tid >> 4, c4 = (tid & 15) << 2;
#pragma unroll
        for (int i = 0; i < 4; i++) {
            float4 v = *(const float4*)(w + (size_t)(k0 + r + i * 16) * N + n0 + c4);
            t[r + i * 16][c4 + 0] = v.x;
            t[r + i * 16][c4 + 1] = v.y;
            t[r + i * 16][c4 + 2] = v.z;
            t[r + i * 16][c4 + 3] = v.w;
        }
    }
    __syncthreads();
    {
        int nl = tid >> 2, kc = (tid & 3) << 4;
        __half hv[16];
#pragma unroll
        for (int i = 0; i < 16; i++)
            hv[i] = __float2half(t[kc + i][nl]);
        *(uint4*)(t16 + (size_t)(n0 + nl) * K + k0 + kc)     = *(uint4*)&hv[0];
        *(uint4*)(t16 + (size_t)(n0 + nl) * K + k0 + kc + 8) = *(uint4*)&hv[8];
    }
}

// ========== fused RoPE + optional scale, strided fp32 src -> fp16 ==========
__global__ void rope_h(const float* __restrict__ t,
                       const float* __restrict__ fc, const float* __restrict__ fs,
                       __half* __restrict__ o, int nheads, int total, float scl,
                       int tok_stride_f2, int tok_off_f2)
{
    int idx = blockIdx.x * blockDim.x + threadIdx.x;
    if (idx >= total) return;
    int pairs = 64 * nheads;
    int tok = idx / pairs;
    int within = idx - tok * pairs;
    int j = idx & 63;
    int s = tok % SEQ;
    float c = fc[s * 64 + j], sn = fs[s * 64 + j];
    float2 v = ((const float2*)t)[(size_t)tok * tok_stride_f2 + tok_off_f2 + within];
    float re = (v.x * c - v.y * sn) * scl;
    float im = (v.x * sn + v.y * c) * scl;
    ((__half2*)o)[idx] = __floats2half2_rn(re, im);
}

// ================= fp16 HMMA flash attention (unchanged) ==========
#define AT_LDS 272
#define AT_QT  (128 * AT_LDS)
#define AT_KVT (64 * AT_LDS)
#define AT_STG (2 * AT_KVT)
#define ATTN_SMEM (AT_QT + 2 * AT_STG)

__global__ void __launch_bounds__(256, 1) attn_h(
    const __half* __restrict__ Qh, const __half* __restrict__ Kh,
    const __half* __restrict__ Vh, __half* __restrict__ Oh)
{
    extern __shared__ char sm_[];
    uint32_t sb = smem_u32(sm_);
    const int tid = threadIdx.x, wid = tid >> 5, lane = tid & 31;
    const int qt = gridDim.x - 1 - blockIdx.x;
    const int h = blockIdx.y, b = blockIdx.z;
    const int q0 = qt * 128, kvh = h >> 2;
    const int nkv = 2 * qt + 2;

    const char* Qg = (const char*)(Qh + ((size_t)(b * SEQ + q0) * NH + h) * HD);
    const char* Kg = (const char*)(Kh + ((size_t)(b * SEQ) * NKV + kvh) * HD);
    const char* Vg = (const char*)(Vh + ((size_t)(b * SEQ) * NKV + kvh) * HD);

    for (int c = tid; c < 128 * 16; c += 256) {
        int r = c >> 4, ch = (c & 15) << 4;
        cp16(sb + r * AT_LDS + ch, Qg + (size_t)r * 8192 + ch);
    }
    auto load_kv = [&](int kt, int s) {
        uint32_t st = sb + AT_QT + s * AT_STG;
        size_t gof = (size_t)kt * 64 * 2048;
        for (int c = tid; c < 64 * 16; c += 256) {
            int r = c >> 4, ch = (c & 15) << 4;
            size_t g = gof + (size_t)r * 2048 + ch;
            cp16(st + r * AT_LDS + ch,          Kg + g);
            cp16(st + AT_KVT + r * AT_LDS + ch, Vg + g);
        }
    };
    load_kv(0, 0);
    cp_commit();

    uint32_t qf[8][4];
    float oacc[16][4];
#pragma unroll
    for (int i = 0; i < 16; i++)
#pragma unroll
        for (int r = 0; r < 4; r++) oacc[i][r] = 0.f;
    float mrow0 = -1e30f, mrow1 = -1e30f, lrow0 = 0.f, lrow1 = 0.f;

    const int bg = lane >> 3;
    const int kb_row = ((bg >> 1) << 3) + (lane & 7);
    const int kb_col = (bg & 1) << 3;

    for (int kt = 0; kt < nkv; kt++) {
        if (kt + 1 < nkv) { load_kv(kt + 1, (kt + 1) & 1); cp_commit(); cp_wait1(); }
        else             { cp_wait0(); }
        __syncthreads();

        if (kt == 0) {
            uint32_t qa = sb + (wid * 16 + (lane & 15)) * AT_LDS + ((lane >> 4) << 3) * 2;
#pragma unroll
            for (int kc = 0; kc < 8; kc++)
                ldsm4(qf[kc][0], qf[kc][1], qf[kc][2], qf[kc][3], qa + kc * 32);
        }
        uint32_t st = sb + AT_QT + (kt & 1) * AT_STG;

        float sacc[8][4];
#pragma unroll
        for (int i = 0; i < 8; i++)
#pragma unroll
            for (int r = 0; r < 4; r++) sacc[i][r] = 0.f;

#pragma unroll
        for (int kc = 0; kc < 8; kc++) {
#pragma unroll
            for (int pr = 0; pr < 4; pr++) {
                uint32_t bd = st + (pr * 16 + kb_row) * AT_LDS + (kc * 16 + kb_col) * 2;
                uint32_t k0r, k1r, k2r, k3r;
                ldsm4(k0r, k1r, k2r, k3r, bd);
                mma16816(sacc[2*pr],   qf[kc], k0r, k1r);
                mma16816(sacc[2*pr+1], qf[kc], k2r, k3r);
            }
        }

        const int k0g = kt * 64;
        const int rlo = q0 + wid * 16 + (lane >> 2);
        if (kt >= nkv - 2) {
#pragma unroll
            for (int nj = 0; nj < 8; nj++) {
                int key = k0g + nj * 8 + ((lane & 3) << 1);
                if (key     > rlo)     sacc[nj][0] = -1e30f;
                if (key + 1 > rlo)     sacc[nj][1] = -1e30f;
                if (key     > rlo + 8) sacc[nj][2] = -1e30f;
                if (key + 1 > rlo + 8) sacc[nj][3] = -1e30f;
            }
        }

        float mx0 = -1e30f, mx1 = -1e30f;
#pragma unroll
        for (int nj = 0; nj < 8; nj++) {
            mx0 = fmaxf(mx0, fmaxf(sacc[nj][0], sacc[nj][1]));
            mx1 = fmaxf(mx1, fmaxf(sacc[nj][2], sacc[nj][3]));
        }
        mx0 = fmaxf(mx0, __shfl_xor_sync(0xffffffffu, mx0, 1));
        mx0 = fmaxf(mx0, __shfl_xor_sync(0xffffffffu, mx0, 2));
        mx1 = fmaxf(mx1, __shfl_xor_sync(0xffffffffu, mx1, 1));
        mx1 = fmaxf(mx1, __shfl_xor_sync(0xffffffffu, mx1, 2));
        float mn0 = fmaxf(mrow0, mx0), mn1 = fmaxf(mrow1, mx1);
        float cr0 = __expf(mrow0 - mn0), cr1 = __expf(mrow1 - mn1);
        mrow0 = mn0; mrow1 = mn1;
        float sum0 = 0.f, sum1 = 0.f;
#pragma unroll
        for (int nj = 0; nj < 8; nj++) {
            float p0 = __expf(sacc[nj][0] - mn0); sacc[nj][0] = p0; sum0 += p0;
            float p1 = __expf(sacc[nj][1] - mn0); sacc[nj][1] = p1; sum0 += p1;
            float p2 = __expf(sacc[nj][2] - mn1); sacc[nj][2] = p2; sum1 += p2;
            float p3 = __expf(sacc[nj][3] - mn1); sacc[nj][3] = p3; sum1 += p3;
        }
        sum0 += __shfl_xor_sync(0xffffffffu, sum0, 1);
        sum0 += __shfl_xor_sync(0xffffffffu, sum0, 2);
        sum1 += __shfl_xor_sync(0xffffffffu, sum1, 1);
        sum1 += __shfl_xor_sync(0xffffffffu, sum1, 2);
        lrow0 = lrow0 * cr0 + sum0;
        lrow1 = lrow1 * cr1 + sum1;
#pragma unroll
        for (int nj = 0; nj < 16; nj++) {
            oacc[nj][0] *= cr0; oacc[nj][1] *= cr0;
            oacc[nj][2] *= cr1; oacc[nj][3] *= cr1;
        }

#pragma unroll
        for (int kc = 0; kc < 4; kc++) {
            uint32_t pa[4];
            pa[0] = packh(sacc[2*kc][0],   sacc[2*kc][1]);
            pa[1] = packh(sacc[2*kc][2],   sacc[2*kc][3]);
            pa[2] = packh(sacc[2*kc+1][0], sacc[2*kc+1][1]);
            pa[3] = packh(sacc[2*kc+1][2], sacc[2*kc+1][3]);
            uint32_t vrow = st + AT_KVT + (kc * 16 + (lane & 15)) * AT_LDS
                          + ((lane >> 4) << 3) * 2;
#pragma unroll
            for (int g = 0; g < 8; g++) {
                uint32_t v0, v1, v2, v3;
                ldsm4t(v0, v1, v2, v3, vrow + g * 32);
                mma16816(oacc[2*g],   pa, v0, v1);
                mma16816(oacc[2*g+1], pa, v2, v3);
            }
        }
        __syncthreads();
    }

    float inv0 = 1.f / lrow0, inv1 = 1.f / lrow1;
    const int rlo = q0 + wid * 16 + (lane >> 2);
    size_t base_lo = ((size_t)(b * SEQ + rlo) * NH + h) * HD + ((lane & 3) << 1);
    size_t base_hi = base_lo + (size_t)8 * NH * HD;
#pragma unroll
    for (int nj = 0; nj < 16; nj++) {
        *(__half2*)(Oh + base_lo + nj * 8) =
            __floats2half2_rn(oacc[nj][0] * inv0, oacc[nj][1] * inv0);
        *(__half2*)(Oh + base_hi + nj * 8) =
            __floats2half2_rn(oacc[nj][2] * inv1, oacc[nj][3] * inv1);
    }
}

// ============================ launch ======================================
extern "C" void kernel_launch(void* const* d_in, const int* in_sizes, int n_in,
                              void* d_out, int out_size)
{
    const float* x  = (const float*)d_in[0];
    const float* wq = (const float*)d_in[1];
    const float* wk = (const float*)d_in[2];
    const float* wv = (const float*)d_in[3];
    const float* wo = (const float*)d_in[4];
    const float* fc = (const float*)d_in[7];
    const float* fs = (const float*)d_in[8];
    float* out = (float*)d_out;
    (void)in_sizes; (void)n_in; (void)out_size;

    float* qkv;
    __half *xh, *wqkvt, *wot, *att, *qh, *kh, *vh;
    cudaGetSymbolAddress((void**)&qkv,   g_qkv);
    cudaGetSymbolAddress((void**)&xh,    g_xh);
    cudaGetSymbolAddress((void**)&wqkvt, g_wqkvt);
    cudaGetSymbolAddress((void**)&wot,   g_wot);
    cudaGetSymbolAddress((void**)&att,   g_att);
    cudaGetSymbolAddress((void**)&qh,    g_qh);
    cudaGetSymbolAddress((void**)&kh,    g_kh);
    cudaGetSymbolAddress((void**)&vh,    g_vh);

    cudaFuncSetAttribute(gemm_h, cudaFuncAttributeMaxDynamicSharedMemorySize, GEMM_SMEM);
    cudaFuncSetAttribute(attn_h, cudaFuncAttributeMaxDynamicSharedMemorySize, ATTN_SMEM);

    // ---- prep ----
    const int n4x = TOKENS * DIMV / 4;
    cvt_kernel<<<n4x / 256, 256>>>(x, xh, n4x);
    tcvt_kernel<<<dim3(DIMV / 64,     DIMV / 64), 256>>>(wq, wqkvt,                          DIMV, DIMV);
    tcvt_kernel<<<dim3(NKV * HD / 64, DIMV / 64), 256>>>(wk, wqkvt + (size_t)DIMV * DIMV,    DIMV, NKV * HD);
    tcvt_kernel<<<dim3(NKV * HD / 64, DIMV / 64), 256>>>(wv, wqkvt + (size_t)(DIMV + NKV*HD) * DIMV, DIMV, NKV * HD);
    tcvt_kernel<<<dim3(DIMV / 64,     DIMV / 64), 256>>>(wo, wot,                            DIMV, DIMV);

    // ---- fused QKV projection ----
    gemm_h<<<dim3(NQKV / BN, TOKENS / BM), 256, GEMM_SMEM>>>(xh, wqkvt, qkv, nullptr, NQKV, DIMV);

    // ---- RoPE / V convert ----
    {
        const float scale = 0.08838834764831845f;
        int tq = TOKENS * NH * 64;
        int tk = TOKENS * NKV * 64;
        rope_h<<<tq / 256, 256>>>(qkv, fc, fs, qh, NH,  tq, scale, NQKV / 2, 0);
        rope_h<<<tk / 256, 256>>>(qkv, fc, fs, kh, NKV, tk, 1.0f,  NQKV / 2, DIMV / 2);
        cvt_v_kernel<<<(TOKENS * 256) / 256, 256>>>(qkv, vh, TOKENS * 256);
    }

    // ---- flash attention ----
    attn_h<<<dim3(SEQ / 128, NH, BATCH_), 256, ATTN_SMEM>>>(qh, kh, vh, att);

    // ---- output projection ----
    gemm_h<<<dim3(DIMV / BN, TOKENS / BM), 256, GEMM_SMEM>>>(att, wot, out, nullptr, DIMV, DIMV);
}

// round 8
// speedup vs baseline: 8.2929x; 1.0015x over previous
#include <cuda_runtime.h>
#include <cuda_fp16.h>
#include <math.h>
#include <stdint.h>

#define BATCH_ 2
#define SEQ    2048
#define DIMV   4096
#define NH     32
#define NKV    8
#define HD     128
#define TOKENS (BATCH_*SEQ)   // 4096
#define NQKV   (DIMV + 2*NKV*HD)   // 6144
#define NSM    148

// ---------------- scratch (no cudaMalloc allowed) ----------------
__device__ __align__(1024) float  g_qkv  [(size_t)TOKENS * NQKV];
__device__ __align__(1024) __half g_xh   [(size_t)TOKENS * DIMV];
__device__ __align__(1024) __half g_wqkvt[(size_t)NQKV * DIMV];
__device__ __align__(1024) __half g_wot  [(size_t)DIMV * DIMV];
__device__ __align__(1024) __half g_att  [(size_t)TOKENS * DIMV];
__device__ __align__(1024) __half g_qh   [(size_t)TOKENS * NH  * HD];
__device__ __align__(1024) __half g_kh   [(size_t)TOKENS * NKV * HD];
__device__ __align__(1024) __half g_vh   [(size_t)TOKENS * NKV * HD];

// ================= helpers =================
__device__ __forceinline__ uint32_t smem_u32(const void* p) {
    return (uint32_t)__cvta_generic_to_shared(p);
}
__device__ __forceinline__ void cp16(uint32_t dst, const void* src) {
    asm volatile("cp.async.cg.shared.global [%0], [%1], 16;" :: "r"(dst), "l"(src));
}
__device__ __forceinline__ void cp_commit() {
    asm volatile("cp.async.commit_group;" ::: "memory");
}
__device__ __forceinline__ void cp_wait1() {
    asm volatile("cp.async.wait_group 1;" ::: "memory");
}
__device__ __forceinline__ void cp_wait0() {
    asm volatile("cp.async.wait_group 0;" ::: "memory");
}
__device__ __forceinline__ void ldsm4(uint32_t& r0, uint32_t& r1, uint32_t& r2, uint32_t& r3,
                                      uint32_t addr) {
    asm volatile("ldmatrix.sync.aligned.m8n8.x4.shared.b16 {%0,%1,%2,%3}, [%4];"
                 : "=r"(r0), "=r"(r1), "=r"(r2), "=r"(r3) : "r"(addr));
}
__device__ __forceinline__ void ldsm4t(uint32_t& r0, uint32_t& r1, uint32_t& r2, uint32_t& r3,
                                       uint32_t addr) {
    asm volatile("ldmatrix.sync.aligned.m8n8.x4.trans.shared.b16 {%0,%1,%2,%3}, [%4];"
                 : "=r"(r0), "=r"(r1), "=r"(r2), "=r"(r3) : "r"(addr));
}
__device__ __forceinline__ void mma16816(float* c, const uint32_t* a, uint32_t b0, uint32_t b1) {
    asm volatile(
        "mma.sync.aligned.m16n8k16.row.col.f32.f16.f16.f32 "
        "{%0,%1,%2,%3}, {%4,%5,%6,%7}, {%8,%9}, {%0,%1,%2,%3};"
        : "+f"(c[0]), "+f"(c[1]), "+f"(c[2]), "+f"(c[3])
        : "r"(a[0]), "r"(a[1]), "r"(a[2]), "r"(a[3]), "r"(b0), "r"(b1));
}
__device__ __forceinline__ uint32_t packh(float a, float b) {
    __half2 t = __floats2half2_rn(a, b);
    return *reinterpret_cast<uint32_t*>(&t);
}

// ========== persistent fp16 HMMA GEMM: C[M,N] = A[M,K] @ B[N,K]^T ==========
// BM=128, BN=128, BK=64, 2-stage cp.async, 8 warps, 2 CTAs/SM, persistent grid.
// Tile order m-fastest: adjacent-in-time tiles share the B block (L2 reuse).
// Numeric path per output element identical to R5-R7.
#define BM 128
#define BN 128
#define BK 64
#define LDSH  144
#define TILEH (128 * LDSH)
#define STGH  (2 * TILEH)
#define GEMM_SMEM (2 * STGH)       // 73728 -> 2 CTAs/SM
#define MT (TOKENS / BM)           // 32

__device__ __forceinline__ void load_stage(
    uint32_t sb, int s, const __half* A, const __half* B, int K, int k0, int tid)
{
    uint32_t st = sb + s * STGH;
#pragma unroll
    for (int t = 0; t < 4; t++) {
        int c = tid + t * 256;
        int row = c >> 3, ch = (c & 7) << 4;
        size_t go = ((size_t)row * K + k0) * 2 + ch;
        cp16(st + row * LDSH + ch,         (const char*)A + go);
        cp16(st + TILEH + row * LDSH + ch, (const char*)B + go);
    }
}

__global__ void __launch_bounds__(256, 2) gemm_h(
    const __half* __restrict__ A, const __half* __restrict__ B,
    float* __restrict__ Cf, __half* __restrict__ Ch, int N, int K, int ntiles)
{
    extern __shared__ char smem[];
    uint32_t sb = smem_u32(smem);
    const int tid = threadIdx.x, wid = tid >> 5, lane = tid & 31;
    const int wm = wid & 1, wn = wid >> 1;

    const int a_row = wm * 64 + (lane & 15);
    const int a_col = (lane >> 4) << 3;
    const int bg = lane >> 3;
    const int b_row = wn * 32 + ((bg >> 1) << 3) + (lane & 7);
    const int b_col = (bg & 1) << 3;
    const int cr = lane >> 2, cc = (lane & 3) << 1;
    const int NIT = K / BK;

    for (int tile = blockIdx.x; tile < ntiles; tile += gridDim.x) {
        const int bm0 = (tile % MT) * BM;           // m-fastest
        const int bn0 = (tile / MT) * BN;
        const __half* pA = A + (size_t)bm0 * K;
        const __half* pB = B + (size_t)bn0 * K;

        float acc[4][4][4];
#pragma unroll
        for (int i = 0; i < 4; i++)
#pragma unroll
            for (int j = 0; j < 4; j++)
#pragma unroll
                for (int r = 0; r < 4; r++) acc[i][j][r] = 0.f;

        load_stage(sb, 0, pA, pB, K, 0, tid);
        cp_commit();

        for (int it = 0; it < NIT; ++it) {
            if (it + 1 < NIT) {
                load_stage(sb, (it + 1) & 1, pA, pB, K, (it + 1) * BK, tid);
                cp_commit();
                cp_wait1();
            } else {
                cp_wait0();
            }
            __syncthreads();

            uint32_t st = sb + (it & 1) * STGH;
#pragma unroll
            for (int ks = 0; ks < 4; ks++) {
                uint32_t af[4][4];
#pragma unroll
                for (int mi = 0; mi < 4; mi++) {
                    uint32_t ad = st + (a_row + mi * 16) * LDSH + (a_col + ks * 16) * 2;
                    ldsm4(af[mi][0], af[mi][1], af[mi][2], af[mi][3], ad);
                }
                uint32_t bf[4][2];
#pragma unroll
                for (int p = 0; p < 2; p++) {
                    uint32_t bd = st + TILEH + (b_row + p * 16) * LDSH + (b_col + ks * 16) * 2;
                    ldsm4(bf[2*p][0], bf[2*p][1], bf[2*p+1][0], bf[2*p+1][1], bd);
                }
#pragma unroll
                for (int mi = 0; mi < 4; mi++)
#pragma unroll
                    for (int ni = 0; ni < 4; ni++)
                        mma16816(acc[mi][ni], af[mi], bf[ni][0], bf[ni][1]);
            }
            __syncthreads();
        }

#pragma unroll
        for (int mi = 0; mi < 4; mi++) {
            int r0 = bm0 + wm * 64 + mi * 16 + cr;
#pragma unroll
            for (int ni = 0; ni < 4; ni++) {
                int col = bn0 + wn * 32 + ni * 8 + cc;
                if (Ch) {
                    *(__half2*)(Ch + (size_t)r0 * N + col) =
                        __floats2half2_rn(acc[mi][ni][0], acc[mi][ni][1]);
                    *(__half2*)(Ch + (size_t)(r0 + 8) * N + col) =
                        __floats2half2_rn(acc[mi][ni][2], acc[mi][ni][3]);
                } else {
                    *(float2*)(Cf + (size_t)r0 * N + col) =
                        make_float2(acc[mi][ni][0], acc[mi][ni][1]);
                    *(float2*)(Cf + (size_t)(r0 + 8) * N + col) =
                        make_float2(acc[mi][ni][2], acc[mi][ni][3]);
                }
            }
        }
        // epilogue touches only registers/gmem; next tile's cp.async writes are
        // ordered for this thread by issue order, others by the first mainloop sync
    }
}

// ================= fp32 -> fp16 convert (packed) =================
__global__ void cvt_kernel(const float* __restrict__ src, __half* __restrict__ dst, int n4)
{
    int i = blockIdx.x * blockDim.x + threadIdx.x;
    if (i >= n4) return;
    float4 v = ((const float4*)src)[i];
    __half2 a = __floats2half2_rn(v.x, v.y);
    __half2 b = __floats2half2_rn(v.z, v.w);
    ((uint2*)dst)[i] = make_uint2(*(uint32_t*)&a, *(uint32_t*)&b);
}

// ======== strided fp32 -> fp16 convert: V slice of fused qkv =========
__global__ void cvt_v_kernel(const float* __restrict__ qkv, __half* __restrict__ dst, int total4)
{
    int i = blockIdx.x * blockDim.x + threadIdx.x;
    if (i >= total4) return;
    int tok = i >> 8, j = i & 255;
    float4 v = ((const float4*)qkv)[(size_t)tok * (NQKV/4) + (DIMV + NKV*HD)/4 + j];
    __half2 a = __floats2half2_rn(v.x, v.y);
    __half2 b = __floats2half2_rn(v.z, v.w);
    ((uint2*)dst)[(size_t)tok * 256 + j] = make_uint2(*(uint32_t*)&a, *(uint32_t*)&b);
}

// ===== transpose + convert: w[K,N] -> wT[N,K] fp16, 64x64 tiles ======
__global__ void __launch_bounds__(256) tcvt_kernel(
    const float* __restrict__ w, __half* __restrict__ t16, int K, int N)
{
    __shared__ float t[64][65];
    const int n0 = blockIdx.x * 64, k0 = blockIdx.y * 64;
    const int tid = threadIdx.x;
    {
        int r = tid >> 4, c4 = (tid & 15) << 2;
#pragma unroll
        for (int i = 0; i < 4; i++) {
            float4 v = *(const float4*)(w + (size_t)(k0 + r + i * 16) * N + n0 + c4);
            t[r + i * 16][c4 + 0] = v.x;
            t[r + i * 16][c4 + 1] = v.y;
            t[r + i * 16][c4 + 2] = v.z;
            t[r + i * 16][c4 + 3] = v.w;
        }
    }
    __syncthreads();
    {
        int nl = tid >> 2, kc = (tid & 3) << 4;
        __half hv[16];
#pragma unroll
        for (int i = 0; i < 16; i++)
            hv[i] = __float2half(t[kc + i][nl]);
        *(uint4*)(t16 + (size_t)(n0 + nl) * K + k0 + kc)     = *(uint4*)&hv[0];
        *(uint4*)(t16 + (size_t)(n0 + nl) * K + k0 + kc + 8) = *(uint4*)&hv[8];
    }
}

// ========== fused RoPE + optional scale, strided fp32 src -> fp16 ==========
__global__ void rope_h(const float* __restrict__ t,
                       const float* __restrict__ fc, const float* __restrict__ fs,
                       __half* __restrict__ o, int nheads, int total, float scl,
                       int tok_stride_f2, int tok_off_f2)
{
    int idx = blockIdx.x * blockDim.x + threadIdx.x;
    if (idx >= total) return;
    int pairs = 64 * nheads;
    int tok = idx / pairs;
    int within = idx - tok * pairs;
    int j = idx & 63;
    int s = tok % SEQ;
    float c = fc[s * 64 + j], sn = fs[s * 64 + j];
    float2 v = ((const float2*)t)[(size_t)tok * tok_stride_f2 + tok_off_f2 + within];
    float re = (v.x * c - v.y * sn) * scl;
    float im = (v.x * sn + v.y * c) * scl;
    ((__half2*)o)[idx] = __floats2half2_rn(re, im);
}

// ========= persistent fp16 HMMA flash attention =========
// Work item w: qt = 15 - (w & 15) (heavy interleaved), h = (w>>4) & 31, b = w>>9.
#define AT_LDS 272
#define AT_QT  (128 * AT_LDS)
#define AT_KVT (64 * AT_LDS)
#define AT_STG (2 * AT_KVT)
#define ATTN_SMEM (AT_QT + 2 * AT_STG)
#define N_ITEMS ((SEQ / 128) * NH * BATCH_)   // 1024

__global__ void __launch_bounds__(256, 1) attn_h(
    const __half* __restrict__ Qh, const __half* __restrict__ Kh,
    const __half* __restrict__ Vh, __half* __restrict__ Oh)
{
    extern __shared__ char sm_[];
    uint32_t sb = smem_u32(sm_);
    const int tid = threadIdx.x, wid = tid >> 5, lane = tid & 31;

    const int bg = lane >> 3;
    const int kb_row = ((bg >> 1) << 3) + (lane & 7);
    const int kb_col = (bg & 1) << 3;

    for (int w = blockIdx.x; w < N_ITEMS; w += gridDim.x) {
        const int qt = 15 - (w & 15);
        const int h = (w >> 4) & 31;
        const int b = w >> 9;
        const int q0 = qt * 128, kvh = h >> 2;
        const int nkv = 2 * qt + 2;

        const char* Qg = (const char*)(Qh + ((size_t)(b * SEQ + q0) * NH + h) * HD);
        const char* Kg = (const char*)(Kh + ((size_t)(b * SEQ) * NKV + kvh) * HD);
        const char* Vg = (const char*)(Vh + ((size_t)(b * SEQ) * NKV + kvh) * HD);

        for (int c = tid; c < 128 * 16; c += 256) {
            int r = c >> 4, ch = (c & 15) << 4;
            cp16(sb + r * AT_LDS + ch, Qg + (size_t)r * 8192 + ch);
        }
        auto load_kv = [&](int kt, int s) {
            uint32_t st = sb + AT_QT + s * AT_STG;
            size_t gof = (size_t)kt * 64 * 2048;
            for (int c = tid; c < 64 * 16; c += 256) {
                int r = c >> 4, ch = (c & 15) << 4;
                size_t g = gof + (size_t)r * 2048 + ch;
                cp16(st + r * AT_LDS + ch,          Kg + g);
                cp16(st + AT_KVT + r * AT_LDS + ch, Vg + g);
            }
        };
        load_kv(0, 0);
        cp_commit();

        uint32_t qf[8][4];
        float oacc[16][4];
#pragma unroll
        for (int i = 0; i < 16; i++)
#pragma unroll
            for (int r = 0; r < 4; r++) oacc[i][r] = 0.f;
        float mrow0 = -1e30f, mrow1 = -1e30f, lrow0 = 0.f, lrow1 = 0.f;

        for (int kt = 0; kt < nkv; kt++) {
            if (kt + 1 < nkv) { load_kv(kt + 1, (kt + 1) & 1); cp_commit(); cp_wait1(); }
            else             { cp_wait0(); }
            __syncthreads();

            if (kt == 0) {
                uint32_t qa = sb + (wid * 16 + (lane & 15)) * AT_LDS + ((lane >> 4) << 3) * 2;
#pragma unroll
                for (int kc = 0; kc < 8; kc++)
                    ldsm4(qf[kc][0], qf[kc][1], qf[kc][2], qf[kc][3], qa + kc * 32);
            }
            uint32_t st = sb + AT_QT + (kt & 1) * AT_STG;

            float sacc[8][4];
#pragma unroll
            for (int i = 0; i < 8; i++)
#pragma unroll
                for (int r = 0; r < 4; r++) sacc[i][r] = 0.f;

#pragma unroll
            for (int kc = 0; kc < 8; kc++) {
#pragma unroll
                for (int pr = 0; pr < 4; pr++) {
                    uint32_t bd = st + (pr * 16 + kb_row) * AT_LDS + (kc * 16 + kb_col) * 2;
                    uint32_t k0r, k1r, k2r, k3r;
                    ldsm4(k0r, k1r, k2r, k3r, bd);
                    mma16816(sacc[2*pr],   qf[kc], k0r, k1r);
                    mma16816(sacc[2*pr+1], qf[kc], k2r, k3r);
                }
            }

            const int k0g = kt * 64;
            const int rlo = q0 + wid * 16 + (lane >> 2);
            if (kt >= nkv - 2) {
#pragma unroll
                for (int nj = 0; nj < 8; nj++) {
                    int key = k0g + nj * 8 + ((lane & 3) << 1);
                    if (key     > rlo)     sacc[nj][0] = -1e30f;
                    if (key + 1 > rlo)     sacc[nj][1] = -1e30f;
                    if (key     > rlo + 8) sacc[nj][2] = -1e30f;
                    if (key + 1 > rlo + 8) sacc[nj][3] = -1e30f;
                }
            }

            float mx0 = -1e30f, mx1 = -1e30f;
#pragma unroll
            for (int nj = 0; nj < 8; nj++) {
                mx0 = fmaxf(mx0, fmaxf(sacc[nj][0], sacc[nj][1]));
                mx1 = fmaxf(mx1, fmaxf(sacc[nj][2], sacc[nj][3]));
            }
            mx0 = fmaxf(mx0, __shfl_xor_sync(0xffffffffu, mx0, 1));
            mx0 = fmaxf(mx0, __shfl_xor_sync(0xffffffffu, mx0, 2));
            mx1 = fmaxf(mx1, __shfl_xor_sync(0xffffffffu, mx1, 1));
            mx1 = fmaxf(mx1, __shfl_xor_sync(0xffffffffu, mx1, 2));
            float mn0 = fmaxf(mrow0, mx0), mn1 = fmaxf(mrow1, mx1);
            float cr0 = __expf(mrow0 - mn0), cr1 = __expf(mrow1 - mn1);
            mrow0 = mn0; mrow1 = mn1;
            float sum0 = 0.f, sum1 = 0.f;
#pragma unroll
            for (int nj = 0; nj < 8; nj++) {
                float p0 = __expf(sacc[nj][0] - mn0); sacc[nj][0] = p0; sum0 += p0;
                float p1 = __expf(sacc[nj][1] - mn0); sacc[nj][1] = p1; sum0 += p1;
                float p2 = __expf(sacc[nj][2] - mn1); sacc[nj][2] = p2; sum1 += p2;
                float p3 = __expf(sacc[nj][3] - mn1); sacc[nj][3] = p3; sum1 += p3;
            }
            sum0 += __shfl_xor_sync(0xffffffffu, sum0, 1);
            sum0 += __shfl_xor_sync(0xffffffffu, sum0, 2);
            sum1 += __shfl_xor_sync(0xffffffffu, sum1, 1);
            sum1 += __shfl_xor_sync(0xffffffffu, sum1, 2);
            lrow0 = lrow0 * cr0 + sum0;
            lrow1 = lrow1 * cr1 + sum1;
#pragma unroll
            for (int nj = 0; nj < 16; nj++) {
                oacc[nj][0] *= cr0; oacc[nj][1] *= cr0;
                oacc[nj][2] *= cr1; oacc[nj][3] *= cr1;
            }

#pragma unroll
            for (int kc = 0; kc < 4; kc++) {
                uint32_t pa[4];
                pa[0] = packh(sacc[2*kc][0],   sacc[2*kc][1]);
                pa[1] = packh(sacc[2*kc][2],   sacc[2*kc][3]);
                pa[2] = packh(sacc[2*kc+1][0], sacc[2*kc+1][1]);
                pa[3] = packh(sacc[2*kc+1][2], sacc[2*kc+1][3]);
                uint32_t vrow = st + AT_KVT + (kc * 16 + (lane & 15)) * AT_LDS
                              + ((lane >> 4) << 3) * 2;
#pragma unroll
                for (int g = 0; g < 8; g++) {
                    uint32_t v0, v1, v2, v3;
                    ldsm4t(v0, v1, v2, v3, vrow + g * 32);
                    mma16816(oacc[2*g],   pa, v0, v1);
                    mma16816(oacc[2*g+1], pa, v2, v3);
                }
            }
            __syncthreads();
        }

        float inv0 = 1.f / lrow0, inv1 = 1.f / lrow1;
        const int rlo = q0 + wid * 16 + (lane >> 2);
        size_t base_lo = ((size_t)(b * SEQ + rlo) * NH + h) * HD + ((lane & 3) << 1);
        size_t base_hi = base_lo + (size_t)8 * NH * HD;
#pragma unroll
        for (int nj = 0; nj < 16; nj++) {
            *(__half2*)(Oh + base_lo + nj * 8) =
                __floats2half2_rn(oacc[nj][0] * inv0, oacc[nj][1] * inv0);
            *(__half2*)(Oh + base_hi + nj * 8) =
                __floats2half2_rn(oacc[nj][2] * inv1, oacc[nj][3] * inv1);
        }
    }
}

// ============================ launch ======================================
extern "C" void kernel_launch(void* const* d_in, const int* in_sizes, int n_in,
                              void* d_out, int out_size)
{
    const float* x  = (const float*)d_in[0];
    const float* wq = (const float*)d_in[1];
    const float* wk = (const float*)d_in[2];
    const float* wv = (const float*)d_in[3];
    const float* wo = (const float*)d_in[4];
    const float* fc = (const float*)d_in[7];
    const float* fs = (const float*)d_in[8];
    float* out = (float*)d_out;
    (void)in_sizes; (void)n_in; (void)out_size;

    float* qkv;
    __half *xh, *wqkvt, *wot, *att, *qh, *kh, *vh;
    cudaGetSymbolAddress((void**)&qkv,   g_qkv);
    cudaGetSymbolAddress((void**)&xh,    g_xh);
    cudaGetSymbolAddress((void**)&wqkvt, g_wqkvt);
    cudaGetSymbolAddress((void**)&wot,   g_wot);
    cudaGetSymbolAddress((void**)&att,   g_att);
    cudaGetSymbolAddress((void**)&qh,    g_qh);
    cudaGetSymbolAddress((void**)&kh,    g_kh);
    cudaGetSymbolAddress((void**)&vh,    g_vh);

    cudaFuncSetAttribute(gemm_h, cudaFuncAttributeMaxDynamicSharedMemorySize, GEMM_SMEM);
    cudaFuncSetAttribute(attn_h, cudaFuncAttributeMaxDynamicSharedMemorySize, ATTN_SMEM);

    // ---- prep ----
    const int n4x = TOKENS * DIMV / 4;
    cvt_kernel<<<n4x / 256, 256>>>(x, xh, n4x);
    tcvt_kernel<<<dim3(DIMV / 64,     DIMV / 64), 256>>>(wq, wqkvt,                          DIMV, DIMV);
    tcvt_kernel<<<dim3(NKV * HD / 64, DIMV / 64), 256>>>(wk, wqkvt + (size_t)DIMV * DIMV,    DIMV, NKV * HD);
    tcvt_kernel<<<dim3(NKV * HD / 64, DIMV / 64), 256>>>(wv, wqkvt + (size_t)(DIMV + NKV*HD) * DIMV, DIMV, NKV * HD);
    tcvt_kernel<<<dim3(DIMV / 64,     DIMV / 64), 256>>>(wo, wot,                            DIMV, DIMV);

    // ---- fused QKV projection (persistent grid, 2 CTAs/SM) ----
    gemm_h<<<2 * NSM, 256, GEMM_SMEM>>>(xh, wqkvt, qkv, nullptr, NQKV, DIMV, MT * (NQKV / BN));

    // ---- RoPE / V convert ----
    {
        const float scale = 0.08838834764831845f;
        int tq = TOKENS * NH * 64;
        int tk = TOKENS * NKV * 64;
        rope_h<<<tq / 256, 256>>>(qkv, fc, fs, qh, NH,  tq, scale, NQKV / 2, 0);
        rope_h<<<tk / 256, 256>>>(qkv, fc, fs, kh, NKV, tk, 1.0f,  NQKV / 2, DIMV / 2);
        cvt_v_kernel<<<(TOKENS * 256) / 256, 256>>>(qkv, vh, TOKENS * 256);
    }

    // ---- flash attention (persistent grid) ----
    attn_h<<<NSM, 256, ATTN_SMEM>>>(qh, kh, vh, att);

    // ---- output projection (persistent grid) ----
    gemm_h<<<2 * NSM, 256, GEMM_SMEM>>>(att, wot, out, nullptr, DIMV, DIMV, MT * (DIMV / BN));
}